// round 3
// baseline (speedup 1.0000x reference)
#include <cuda_runtime.h>

#define B_ 32
#define N_ 4096
#define DU_ 64
#define D_ 128
#define NTILES 32                 // N_/128
#define TOTAL_BLOCKS (B_ * NTILES)

// Scratch (allocation-free rule: __device__ globals)
__device__ float g_part[B_][NTILES][256];   // per-tile moment partials [h*128+j]
__device__ float g_apart[B_][NTILES][2];    // per-tile alpha-sum partials
__device__ int   g_done;                    // zero-initialized at load; reset by last block

__device__ __forceinline__ float fast_tanh(float y) {
    float e = __expf(2.0f * y);
    return 1.0f - 2.0f / (e + 1.0f);
}
__device__ __forceinline__ float gelu_tanh(float x) {
    const float k0 = 0.7978845608028654f; // sqrt(2/pi)
    float inner = k0 * (x + 0.044715f * x * x * x);
    return 0.5f * x * (1.0f + fast_tanh(inner));
}
__device__ __forceinline__ unsigned f2tf32(float x) {
    unsigned y;
    asm("cvt.rna.tf32.f32 %0, %1;" : "=r"(y) : "f"(x));
    return y;
}
__device__ __forceinline__ void mma8(float* c, const unsigned* a, unsigned b0, unsigned b1) {
    asm volatile(
        "mma.sync.aligned.m16n8k8.row.col.f32.tf32.tf32.f32 "
        "{%0,%1,%2,%3}, {%4,%5,%6,%7}, {%8,%9}, {%0,%1,%2,%3};\n"
        : "+f"(c[0]), "+f"(c[1]), "+f"(c[2]), "+f"(c[3])
        : "r"(a[0]), "r"(a[1]), "r"(a[2]), "r"(a[3]), "r"(b0), "r"(b1));
}

// ---------------------------------------------------------------------------
// SMEM layout (floats)
// ---------------------------------------------------------------------------
#define OFF_U    0        // 128 x 68   (A, tf32)
#define OFF_W1   8704     // 64  x 136  (B, tf32)
#define OFF_Z1   17408    // 128 x 132  (A, tf32)
#define OFF_W2   34304    // 128 x 136  (B, tf32)
#define OFF_WT   51712    // 256 wt + [256..257] = c0,c1 (pad to 264)
#define OFF_AL   51976    // 256 alpha
#define OFF_SCR  52232    // 768 scratch: q-partials[512], qs[512..639]; stage3 partials[512]
#define OFF_FLAG 53000    // 1 int
#define SMEM_FLOATS 53004
// Aliases (regions dead by the time they're reused):
//   sZ2  = sm + 0        : 128 x 129 fp32  (over sU+sW1, after stage 1)
//   m_sh = sm + OFF_W2   : 32 x 2 x 128    (epilogue, after stage 2)
//   ov_sh= sm + OFF_Z1   : 32 x 128        (epilogue)
//   ab_sh= sm + OFF_WT   : 64              (epilogue)

__global__ __launch_bounds__(512, 1)
void main_kernel(const float* __restrict__ u,
                 const float* __restrict__ W1, const float* __restrict__ b1,
                 const float* __restrict__ W2, const float* __restrict__ b2,
                 const float* __restrict__ embed,
                 const float* __restrict__ Wq, const float* __restrict__ bq,
                 const float* __restrict__ Wk, const float* __restrict__ bk,
                 const float* __restrict__ Wv, const float* __restrict__ bv,
                 const float* __restrict__ Wo, const float* __restrict__ bo,
                 float* __restrict__ out) {
    extern __shared__ float sm[];
    float* sU   = sm + OFF_U;
    float* sW1  = sm + OFF_W1;
    float* sZ1  = sm + OFF_Z1;
    float* sW2  = sm + OFF_W2;
    float* sWT  = sm + OFF_WT;
    float* sAl  = sm + OFF_AL;
    float* sScr = sm + OFF_SCR;
    int*   sFlag = (int*)(sm + OFF_FLAG);
    float* sZ2  = sm;  // alias

    const int tid = threadIdx.x;
    const int bidx = blockIdx.x;
    const int b = bidx >> 5;
    const int tile = bidx & 31;
    const int row0 = tile * 128;

    // ======== Phase 0: stage tiles (tf32) + q partials ========
    {   // u tile: 128 x 64 -> 2048 float4
        const float4* src = (const float4*)(u + ((size_t)b * N_ + row0) * DU_);
        #pragma unroll
        for (int it = 0; it < 4; it++) {
            int i = tid + it * 512;
            int r = i >> 4, c4 = i & 15;
            float4 v = src[i];
            float* d = &sU[r * 68 + c4 * 4];
            d[0] = __uint_as_float(f2tf32(v.x));
            d[1] = __uint_as_float(f2tf32(v.y));
            d[2] = __uint_as_float(f2tf32(v.z));
            d[3] = __uint_as_float(f2tf32(v.w));
        }
    }
    {   // W1: 64 x 128 -> stride 136
        const float4* src = (const float4*)W1;
        #pragma unroll
        for (int it = 0; it < 4; it++) {
            int i = tid + it * 512;
            int r = i >> 5, c4 = i & 31;
            float4 v = src[i];
            float* d = &sW1[r * 136 + c4 * 4];
            d[0] = __uint_as_float(f2tf32(v.x));
            d[1] = __uint_as_float(f2tf32(v.y));
            d[2] = __uint_as_float(f2tf32(v.z));
            d[3] = __uint_as_float(f2tf32(v.w));
        }
    }
    {   // W2: 128 x 128 -> stride 136
        const float4* src = (const float4*)W2;
        #pragma unroll
        for (int it = 0; it < 8; it++) {
            int i = tid + it * 512;
            int r = i >> 5, c4 = i & 31;
            float4 v = src[i];
            float* d = &sW2[r * 136 + c4 * 4];
            d[0] = __uint_as_float(f2tf32(v.x));
            d[1] = __uint_as_float(f2tf32(v.y));
            d[2] = __uint_as_float(f2tf32(v.z));
            d[3] = __uint_as_float(f2tf32(v.w));
        }
    }
    {   // q partials: 4 quarters x 128 outputs
        int j = tid & 127, qtr = tid >> 7;
        float p = 0.f;
        #pragma unroll 8
        for (int i = qtr * 32; i < qtr * 32 + 32; i++) p += embed[i] * Wq[i * 128 + j];
        sScr[qtr * 128 + j] = p;
    }
    __syncthreads();

    // ======== Phase 1: qs combine ========
    if (tid < 128) {
        float s = bq[tid] + sScr[tid] + sScr[128 + tid] + sScr[256 + tid] + sScr[384 + tid];
        sScr[512 + tid] = s;
    }
    __syncthreads();

    // ======== Phase 2: w~ and c ========
    if (tid < 256) {
        int h = tid >> 7, i = tid & 127;
        const float* qh = &sScr[512 + h * 64];
        float s = 0.f;
        #pragma unroll 8
        for (int d = 0; d < 64; d++) s += Wk[i * 128 + h * 64 + d] * qh[d];
        sWT[tid] = s;
    }
    if (tid < 2) {
        const float* qh = &sScr[512 + tid * 64];
        float s = 0.f;
        #pragma unroll 8
        for (int d = 0; d < 64; d++) s += bk[tid * 64 + d] * qh[d];
        sWT[256 + tid] = s;
    }
    __syncthreads();

    const int lane = tid & 31, warp = tid >> 5;
    const int wm = warp & 3, wn = warp >> 2;   // 4 x 4 warp grid
    const int g = lane >> 2, t = lane & 3;

    float acc[2][4][4];

    // ======== Stage 1: Z1 = gelu(U @ W1 + b1), K=64 ========
    #pragma unroll
    for (int mt = 0; mt < 2; mt++)
        #pragma unroll
        for (int nt = 0; nt < 4; nt++)
            #pragma unroll
            for (int e = 0; e < 4; e++) acc[mt][nt][e] = 0.f;

    #pragma unroll
    for (int k0 = 0; k0 < 64; k0 += 8) {
        unsigned a[2][4];
        #pragma unroll
        for (int mt = 0; mt < 2; mt++) {
            int r = wm * 32 + mt * 16 + g;
            a[mt][0] = __float_as_uint(sU[r * 68 + k0 + t]);
            a[mt][1] = __float_as_uint(sU[(r + 8) * 68 + k0 + t]);
            a[mt][2] = __float_as_uint(sU[r * 68 + k0 + t + 4]);
            a[mt][3] = __float_as_uint(sU[(r + 8) * 68 + k0 + t + 4]);
        }
        #pragma unroll
        for (int nt = 0; nt < 4; nt++) {
            int n = wn * 32 + nt * 8 + g;
            unsigned b0 = __float_as_uint(sW1[(k0 + t) * 136 + n]);
            unsigned bb = __float_as_uint(sW1[(k0 + t + 4) * 136 + n]);
            mma8(acc[0][nt], a[0], b0, bb);
            mma8(acc[1][nt], a[1], b0, bb);
        }
    }
    #pragma unroll
    for (int nt = 0; nt < 4; nt++) {
        int c0 = wn * 32 + nt * 8 + 2 * t;
        float bc0 = __ldg(&b1[c0]), bc1 = __ldg(&b1[c0 + 1]);
        #pragma unroll
        for (int mt = 0; mt < 2; mt++) {
            int r = wm * 32 + mt * 16 + g;
            sZ1[r * 132 + c0]           = __uint_as_float(f2tf32(gelu_tanh(acc[mt][nt][0] + bc0)));
            sZ1[r * 132 + c0 + 1]       = __uint_as_float(f2tf32(gelu_tanh(acc[mt][nt][1] + bc1)));
            sZ1[(r + 8) * 132 + c0]     = __uint_as_float(f2tf32(gelu_tanh(acc[mt][nt][2] + bc0)));
            sZ1[(r + 8) * 132 + c0 + 1] = __uint_as_float(f2tf32(gelu_tanh(acc[mt][nt][3] + bc1)));
        }
    }
    __syncthreads();

    // ======== Stage 2: Z2 = gelu(Z1 @ W2 + b2), K=128 ========
    #pragma unroll
    for (int mt = 0; mt < 2; mt++)
        #pragma unroll
        for (int nt = 0; nt < 4; nt++)
            #pragma unroll
            for (int e = 0; e < 4; e++) acc[mt][nt][e] = 0.f;

    #pragma unroll
    for (int k0 = 0; k0 < 128; k0 += 8) {
        unsigned a[2][4];
        #pragma unroll
        for (int mt = 0; mt < 2; mt++) {
            int r = wm * 32 + mt * 16 + g;
            a[mt][0] = __float_as_uint(sZ1[r * 132 + k0 + t]);
            a[mt][1] = __float_as_uint(sZ1[(r + 8) * 132 + k0 + t]);
            a[mt][2] = __float_as_uint(sZ1[r * 132 + k0 + t + 4]);
            a[mt][3] = __float_as_uint(sZ1[(r + 8) * 132 + k0 + t + 4]);
        }
        #pragma unroll
        for (int nt = 0; nt < 4; nt++) {
            int n = wn * 32 + nt * 8 + g;
            unsigned b0 = __float_as_uint(sW2[(k0 + t) * 136 + n]);
            unsigned bb = __float_as_uint(sW2[(k0 + t + 4) * 136 + n]);
            mma8(acc[0][nt], a[0], b0, bb);
            mma8(acc[1][nt], a[1], b0, bb);
        }
    }
    __syncthreads();   // sZ2 aliases sU/sW1 — ensure stage-2 A reads done chipwide? (block-local: reads above finished)
    #pragma unroll
    for (int nt = 0; nt < 4; nt++) {
        int c0 = wn * 32 + nt * 8 + 2 * t;
        float bc0 = __ldg(&b2[c0]), bc1 = __ldg(&b2[c0 + 1]);
        #pragma unroll
        for (int mt = 0; mt < 2; mt++) {
            int r = wm * 32 + mt * 16 + g;
            sZ2[r * 129 + c0]           = gelu_tanh(acc[mt][nt][0] + bc0);
            sZ2[r * 129 + c0 + 1]       = gelu_tanh(acc[mt][nt][1] + bc1);
            sZ2[(r + 8) * 129 + c0]     = gelu_tanh(acc[mt][nt][2] + bc0);
            sZ2[(r + 8) * 129 + c0 + 1] = gelu_tanh(acc[mt][nt][3] + bc1);
        }
    }
    __syncthreads();

    // ======== Stage 3a: alpha[h][r] (split 2 halves over j) ========
    {
        int half = tid >> 8, task = tid & 255;
        int r = task & 127, h = task >> 7;
        const float* wt = &sWT[h * 128];
        const float* zr = &sZ2[r * 129];
        float p = 0.f;
        #pragma unroll 8
        for (int j = half * 64; j < half * 64 + 64; j++) p += zr[j] * wt[j];
        sScr[half * 256 + task] = p;
    }
    __syncthreads();
    if (tid < 256) {
        int r = tid & 127, h = tid >> 7;
        sAl[h * 128 + r] = sScr[tid] + sScr[256 + tid] + sWT[256 + h];
    }
    __syncthreads();

    // ======== Stage 3b: moments (split 2 halves over r) + abar ========
    {
        int half = tid >> 8, task = tid & 255;
        int j = task & 127, h = task >> 7;
        const float* al = &sAl[h * 128];
        float m = 0.f;
        #pragma unroll 8
        for (int r = half * 64; r < half * 64 + 64; r++) m += al[r] * sZ2[r * 129 + j];
        sScr[half * 256 + task] = m;
    }
    __syncthreads();
    if (tid < 256) {
        g_part[b][tile][tid] = sScr[tid] + sScr[256 + tid];
    }
    if (tid < 2) {
        const float* al = &sAl[tid * 128];
        float s = 0.f;
        #pragma unroll 8
        for (int r = 0; r < 128; r++) s += al[r];
        g_apart[b][tile][tid] = s;
    }

    // ======== Last-block epilogue ========
    if (tid == 0) {
        __threadfence();
        int prev = atomicAdd(&g_done, 1);
        sFlag[0] = (prev == TOTAL_BLOCKS - 1) ? 1 : 0;
    }
    __syncthreads();
    if (!sFlag[0]) return;
    __threadfence();

    float* m_sh  = sm + OFF_W2;   // 32*256
    float* ov_sh = sm + OFF_Z1;   // 32*128
    float* ab_sh = sm + OFF_WT;   // 64
    const float invN = 1.0f / (float)N_;

    // E1: reduce partials over tiles
    const float* gp = &g_part[0][0][0];
    #pragma unroll
    for (int it = 0; it < 16; it++) {
        int idx = tid + it * 512;              // idx = bb*256 + hp
        int bb = idx >> 8, hp = idx & 255;
        float s = 0.f;
        #pragma unroll 8
        for (int tt = 0; tt < NTILES; tt++) s += gp[(bb * NTILES + tt) * 256 + hp];
        m_sh[idx] = s;
    }
    if (tid < 64) {
        int bb = tid >> 1, h = tid & 1;
        float s = 0.f;
        #pragma unroll 8
        for (int tt = 0; tt < NTILES; tt++) s += g_apart[bb][tt][h];
        ab_sh[tid] = s;
    }
    __syncthreads();

    // E2: ov[bb][j] = (abar*bv[j] + m . Wv[:,j]) / N
    #pragma unroll
    for (int it = 0; it < 8; it++) {
        int idx = tid + it * 512;              // idx = bb*128 + j
        int bb = idx >> 7, j = idx & 127, h = j >> 6;
        float s = ab_sh[bb * 2 + h] * bv[j];
        const float* mm = &m_sh[bb * 256 + h * 128];
        #pragma unroll 8
        for (int p = 0; p < 128; p++) s += mm[p] * Wv[p * 128 + j];
        ov_sh[idx] = s * invN;
    }
    __syncthreads();

    // E3: out[bb][j] = bo[j] + ov . Wo[:,j]
    #pragma unroll
    for (int it = 0; it < 8; it++) {
        int idx = tid + it * 512;
        int bb = idx >> 7, j = idx & 127;
        float o = bo[j];
        const float* ov = &ov_sh[bb * 128];
        #pragma unroll 8
        for (int p = 0; p < 128; p++) o += ov[p] * Wo[p * 128 + j];
        out[idx] = o;
    }

    if (tid == 0) atomicExch(&g_done, 0);   // reset for next replay
}

// ---------------------------------------------------------------------------
extern "C" void kernel_launch(void* const* d_in, const int* in_sizes, int n_in,
                              void* d_out, int out_size) {
    const float* u     = (const float*)d_in[0];
    // d_in[1] = x : unused by the reference
    const float* W1    = (const float*)d_in[2];
    const float* b1    = (const float*)d_in[3];
    const float* W2    = (const float*)d_in[4];
    const float* b2    = (const float*)d_in[5];
    const float* embed = (const float*)d_in[6];
    const float* Wq    = (const float*)d_in[7];
    const float* bq    = (const float*)d_in[8];
    const float* Wk    = (const float*)d_in[9];
    const float* bk    = (const float*)d_in[10];
    const float* Wv    = (const float*)d_in[11];
    const float* bv    = (const float*)d_in[12];
    const float* Wo    = (const float*)d_in[13];
    const float* bo    = (const float*)d_in[14];
    float* out = (float*)d_out;

    const size_t smem_bytes = (size_t)SMEM_FLOATS * sizeof(float);  // 212,016 B
    cudaFuncSetAttribute(main_kernel, cudaFuncAttributeMaxDynamicSharedMemorySize,
                         (int)smem_bytes);

    main_kernel<<<TOTAL_BLOCKS, 512, smem_bytes>>>(
        u, W1, b1, W2, b2, embed, Wq, bq, Wk, bk, Wv, bv, Wo, bo, out);
}

// round 4
// speedup vs baseline: 2.7231x; 2.7231x over previous
#include <cuda_runtime.h>

#define B_ 32
#define N_ 4096
#define DU_ 64
#define D_ 128
#define NTILES 32                 // N_/128
#define NTOT (B_ * NTILES)        // 1024 tiles
#define GRID_MAIN 148

// Scratch (allocation-free rule: __device__ globals)
__device__ float g_wt[256];                 // w~ flat [h*128+i]
__device__ float g_c[2];                    // q_h . bk_h
__device__ float g_part[B_][NTILES][256];   // per-tile moment partials [h*128+j]
__device__ float g_apart[B_][NTILES][2];    // per-tile alpha-sum partials
__device__ int   g_tile;                    // work counter (reset by setup each replay)

__device__ __forceinline__ float tanh_fast(float x) {
    float y;
    asm("tanh.approx.f32 %0, %1;" : "=f"(y) : "f"(x));
    return y;
}
__device__ __forceinline__ float gelu_tanh(float x) {
    const float k0 = 0.7978845608028654f; // sqrt(2/pi)
    float inner = k0 * (x + 0.044715f * x * x * x);
    return 0.5f * x * (1.0f + tanh_fast(inner));
}
__device__ __forceinline__ unsigned f2tf32(float x) {
    unsigned y;
    asm("cvt.rna.tf32.f32 %0, %1;" : "=r"(y) : "f"(x));
    return y;
}
__device__ __forceinline__ void mma8(float* c, const unsigned* a, unsigned b0, unsigned b1) {
    asm volatile(
        "mma.sync.aligned.m16n8k8.row.col.f32.tf32.tf32.f32 "
        "{%0,%1,%2,%3}, {%4,%5,%6,%7}, {%8,%9}, {%0,%1,%2,%3};\n"
        : "+f"(c[0]), "+f"(c[1]), "+f"(c[2]), "+f"(c[3])
        : "r"(a[0]), "r"(a[1]), "r"(a[2]), "r"(a[3]), "r"(b0), "r"(b1));
}

// ---------------------------------------------------------------------------
// Kernel A: setup. 1 block x 1024 threads. Computes q, w~, c; resets g_tile.
// ---------------------------------------------------------------------------
__global__ __launch_bounds__(1024)
void setup_kernel(const float* __restrict__ embed,
                  const float* __restrict__ Wq, const float* __restrict__ bq,
                  const float* __restrict__ Wk, const float* __restrict__ bk) {
    __shared__ float sq[1152];   // [0..1024) partials, [1024..1152) qs
    int tid = threadIdx.x;

    // qs partials: 8 k-slices x 128 outputs
    {
        int j = tid & 127, sl = tid >> 7;
        float p = 0.f;
        #pragma unroll
        for (int i = sl * 16; i < sl * 16 + 16; i++) p += embed[i] * Wq[i * 128 + j];
        sq[sl * 128 + j] = p;
    }
    __syncthreads();
    if (tid < 128) {
        float s = bq[tid];
        #pragma unroll
        for (int sl = 0; sl < 8; sl++) s += sq[sl * 128 + tid];
        sq[1024 + tid] = s;
    }
    __syncthreads();
    // w~ partials: 4 k-slices x 256 outputs
    {
        int o = tid & 255, sl = tid >> 8;
        int i = o & 127, h = o >> 7;
        float p = 0.f;
        #pragma unroll
        for (int d = sl * 16; d < sl * 16 + 16; d++)
            p += Wk[i * 128 + h * 64 + d] * sq[1024 + h * 64 + d];
        sq[sl * 256 + o] = p;
    }
    __syncthreads();
    if (tid < 256)
        g_wt[tid] = sq[tid] + sq[256 + tid] + sq[512 + tid] + sq[768 + tid];
    if (tid < 2) {
        float s = 0.f;
        #pragma unroll
        for (int d = 0; d < 64; d++) s += bk[tid * 64 + d] * sq[1024 + tid * 64 + d];
        g_c[tid] = s;
    }
    if (tid == 0) g_tile = 0;
}

// ---------------------------------------------------------------------------
// SMEM layout (floats) for persistent main kernel
// ---------------------------------------------------------------------------
#define OFF_W1   0        // 64  x 136 (persistent across tiles)
#define OFF_W2   8704     // 128 x 136 (persistent)
#define OFF_U    26112    // 128 x 68  (per tile)
#define OFF_Z1   34816    // 128 x 132 (per tile)
#define OFF_WT   51712    // 256 wt + [256..257] c  (persistent)
#define OFF_AL   51976    // 256 alpha
#define SMEM_FLOATS 52240
// sZ2 = sm + OFF_U : 128 x 129 fp32, aliases sU + head of sZ1 (dead after
// stage-2 k-loop + barrier).

// Double-buffered fragment load for one 8-wide k-step.
template<int SA, int SB>
__device__ __forceinline__ void load_frags(const float* __restrict__ A,
                                           const float* __restrict__ Bm,
                                           int k0, int wm, int wn, int g, int t,
                                           unsigned a[2][4], unsigned bf[8][2]) {
    #pragma unroll
    for (int mt = 0; mt < 2; mt++) {
        int r = wm * 32 + mt * 16 + g;
        a[mt][0] = __float_as_uint(A[r * SA + k0 + t]);
        a[mt][1] = __float_as_uint(A[(r + 8) * SA + k0 + t]);
        a[mt][2] = __float_as_uint(A[r * SA + k0 + t + 4]);
        a[mt][3] = __float_as_uint(A[(r + 8) * SA + k0 + t + 4]);
    }
    #pragma unroll
    for (int nt = 0; nt < 8; nt++) {
        int n = wn * 64 + nt * 8 + g;
        bf[nt][0] = __float_as_uint(Bm[(k0 + t) * SB + n]);
        bf[nt][1] = __float_as_uint(Bm[(k0 + t + 4) * SB + n]);
    }
}

template<int SA, int SB, int KSTEPS>
__device__ __forceinline__ void gemm_tile(const float* __restrict__ A,
                                          const float* __restrict__ Bm,
                                          float acc[2][8][4],
                                          int wm, int wn, int g, int t) {
    unsigned af[2][2][4];
    unsigned bfr[2][8][2];
    load_frags<SA, SB>(A, Bm, 0, wm, wn, g, t, af[0], bfr[0]);
    #pragma unroll
    for (int s = 0; s < KSTEPS; s++) {
        int cur = s & 1, nxt = cur ^ 1;
        if (s + 1 < KSTEPS)
            load_frags<SA, SB>(A, Bm, (s + 1) * 8, wm, wn, g, t, af[nxt], bfr[nxt]);
        #pragma unroll
        for (int nt = 0; nt < 8; nt++) {
            mma8(acc[0][nt], af[cur][0], bfr[cur][nt][0], bfr[cur][nt][1]);
            mma8(acc[1][nt], af[cur][1], bfr[cur][nt][0], bfr[cur][nt][1]);
        }
    }
}

// ---------------------------------------------------------------------------
// Kernel B: persistent fused MLP + moments. grid=148 x 256 threads (8 warps).
// Warp grid 4(m) x 2(n): warp owns rows [wm*32,+32), cols [wn*64,+64).
// ---------------------------------------------------------------------------
__global__ __launch_bounds__(256, 1)
void main_kernel(const float* __restrict__ u,
                 const float* __restrict__ W1, const float* __restrict__ b1,
                 const float* __restrict__ W2, const float* __restrict__ b2) {
    extern __shared__ float sm[];
    float* sW1 = sm + OFF_W1;
    float* sW2 = sm + OFF_W2;
    float* sU  = sm + OFF_U;
    float* sZ1 = sm + OFF_Z1;
    float* sWT = sm + OFF_WT;
    float* sAl = sm + OFF_AL;
    float* sZ2 = sm + OFF_U;   // alias
    __shared__ int s_tile;

    const int tid = threadIdx.x;
    const int lane = tid & 31, warp = tid >> 5;
    const int wm = warp & 3, wn = warp >> 2;
    const int g = lane >> 2, t = lane & 3;

    // ---- persistent staging: W1, W2 (tf32), wt, c ----
    {
        const float4* src = (const float4*)W1;
        #pragma unroll
        for (int it = 0; it < 8; it++) {
            int i = tid + it * 256;
            int r = i >> 5, c4 = i & 31;
            float4 v = src[i];
            float* d = &sW1[r * 136 + c4 * 4];
            d[0] = __uint_as_float(f2tf32(v.x));
            d[1] = __uint_as_float(f2tf32(v.y));
            d[2] = __uint_as_float(f2tf32(v.z));
            d[3] = __uint_as_float(f2tf32(v.w));
        }
    }
    {
        const float4* src = (const float4*)W2;
        #pragma unroll
        for (int it = 0; it < 16; it++) {
            int i = tid + it * 256;
            int r = i >> 5, c4 = i & 31;
            float4 v = src[i];
            float* d = &sW2[r * 136 + c4 * 4];
            d[0] = __uint_as_float(f2tf32(v.x));
            d[1] = __uint_as_float(f2tf32(v.y));
            d[2] = __uint_as_float(f2tf32(v.z));
            d[3] = __uint_as_float(f2tf32(v.w));
        }
    }
    sWT[tid] = g_wt[tid];
    if (tid < 2) sWT[256 + tid] = g_c[tid];

    float bb1[2], bb2[2];
    {
        int c0 = wn * 64 + 2 * t;   // bias cols used by this thread repeat every 8
        (void)c0;
    }

    // ---- persistent tile loop ----
    for (;;) {
        if (tid == 0) s_tile = atomicAdd(&g_tile, 1);
        __syncthreads();               // publishes s_tile; protects sU/sZ2 reuse
        int tile = s_tile;
        if (tile >= NTOT) break;
        int b = tile >> 5;
        int row0 = (tile & 31) * 128;

        // stage u tile (tf32)
        {
            const float4* src = (const float4*)(u + ((size_t)b * N_ + row0) * DU_);
            #pragma unroll
            for (int it = 0; it < 8; it++) {
                int i = tid + it * 256;
                int r = i >> 4, c4 = i & 15;
                float4 v = src[i];
                float* d = &sU[r * 68 + c4 * 4];
                d[0] = __uint_as_float(f2tf32(v.x));
                d[1] = __uint_as_float(f2tf32(v.y));
                d[2] = __uint_as_float(f2tf32(v.z));
                d[3] = __uint_as_float(f2tf32(v.w));
            }
        }
        __syncthreads();

        // ======== Stage 1: Z1 = gelu(U @ W1 + b1), K=64 ========
        float acc[2][8][4];
        #pragma unroll
        for (int mt = 0; mt < 2; mt++)
            #pragma unroll
            for (int nt = 0; nt < 8; nt++)
                #pragma unroll
                for (int e = 0; e < 4; e++) acc[mt][nt][e] = 0.f;

        gemm_tile<68, 136, 8>(sU, sW1, acc, wm, wn, g, t);

        #pragma unroll
        for (int nt = 0; nt < 8; nt++) {
            int c0 = wn * 64 + nt * 8 + 2 * t;
            float bc0 = __ldg(&b1[c0]), bc1 = __ldg(&b1[c0 + 1]);
            #pragma unroll
            for (int mt = 0; mt < 2; mt++) {
                int r = wm * 32 + mt * 16 + g;
                sZ1[r * 132 + c0]           = __uint_as_float(f2tf32(gelu_tanh(acc[mt][nt][0] + bc0)));
                sZ1[r * 132 + c0 + 1]       = __uint_as_float(f2tf32(gelu_tanh(acc[mt][nt][1] + bc1)));
                sZ1[(r + 8) * 132 + c0]     = __uint_as_float(f2tf32(gelu_tanh(acc[mt][nt][2] + bc0)));
                sZ1[(r + 8) * 132 + c0 + 1] = __uint_as_float(f2tf32(gelu_tanh(acc[mt][nt][3] + bc1)));
            }
        }
        __syncthreads();

        // ======== Stage 2: Z2 = gelu(Z1 @ W2 + b2), K=128 ========
        #pragma unroll
        for (int mt = 0; mt < 2; mt++)
            #pragma unroll
            for (int nt = 0; nt < 8; nt++)
                #pragma unroll
                for (int e = 0; e < 4; e++) acc[mt][nt][e] = 0.f;

        gemm_tile<132, 136, 16>(sZ1, sW2, acc, wm, wn, g, t);

        __syncthreads();   // all sZ1/sU reads done; sZ2 writes may alias them
        #pragma unroll
        for (int nt = 0; nt < 8; nt++) {
            int c0 = wn * 64 + nt * 8 + 2 * t;
            float bc0 = __ldg(&b2[c0]), bc1 = __ldg(&b2[c0 + 1]);
            #pragma unroll
            for (int mt = 0; mt < 2; mt++) {
                int r = wm * 32 + mt * 16 + g;
                sZ2[r * 129 + c0]           = gelu_tanh(acc[mt][nt][0] + bc0);
                sZ2[r * 129 + c0 + 1]       = gelu_tanh(acc[mt][nt][1] + bc1);
                sZ2[(r + 8) * 129 + c0]     = gelu_tanh(acc[mt][nt][2] + bc0);
                sZ2[(r + 8) * 129 + c0 + 1] = gelu_tanh(acc[mt][nt][3] + bc1);
            }
        }
        __syncthreads();

        // ======== Stage 3a: alpha[h][r] ========
        {
            int r = tid & 127, h = tid >> 7;
            const float* wt = &sWT[h * 128];
            const float* zr = &sZ2[r * 129];
            float a = sWT[256 + h];
            #pragma unroll 8
            for (int j = 0; j < 128; j++) a += zr[j] * wt[j];
            sAl[h * 128 + r] = a;
        }
        __syncthreads();

        // ======== Stage 3b: moments + abar, non-atomic per-tile slots ========
        {
            int j = tid & 127, h = tid >> 7;
            const float* al = &sAl[h * 128];
            float m = 0.f;
            #pragma unroll 8
            for (int r = 0; r < 128; r++) m += al[r] * sZ2[r * 129 + j];
            g_part[b][tile & 31][tid] = m;
            if (tid < 2) {
                float s = 0.f;
                #pragma unroll 8
                for (int r = 0; r < 128; r++) s += sAl[tid * 128 + r];
                g_apart[b][tile & 31][tid] = s;
            }
        }
        // loop-top barrier protects sZ2 before next tile's sU staging
    }
}

// ---------------------------------------------------------------------------
// Kernel C: epilogue. grid = B blocks x 128 threads.
// ---------------------------------------------------------------------------
__global__ __launch_bounds__(128)
void epilogue_kernel(const float* __restrict__ Wv, const float* __restrict__ bv,
                     const float* __restrict__ Wo, const float* __restrict__ bo,
                     float* __restrict__ out) {
    __shared__ float m_sh[256];
    __shared__ float ov_sh[128];
    __shared__ float ab_sh[2];
    int b = blockIdx.x;
    int j = threadIdx.x;
    const float invN = 1.0f / (float)N_;

    #pragma unroll
    for (int hp = j; hp < 256; hp += 128) {
        float s = 0.f;
        #pragma unroll 8
        for (int tt = 0; tt < NTILES; tt++) s += g_part[b][tt][hp];
        m_sh[hp] = s;
    }
    if (j < 2) {
        float s = 0.f;
        #pragma unroll 8
        for (int tt = 0; tt < NTILES; tt++) s += g_apart[b][tt][j];
        ab_sh[j] = s;
    }
    __syncthreads();

    {
        int h = j >> 6;
        float s = ab_sh[h] * bv[j];
        const float* mm = &m_sh[h * 128];
        #pragma unroll 8
        for (int p = 0; p < 128; p++) s += mm[p] * Wv[p * 128 + j];
        ov_sh[j] = s * invN;
    }
    __syncthreads();

    {
        float o = bo[j];
        #pragma unroll 8
        for (int p = 0; p < 128; p++) o += ov_sh[p] * Wo[p * 128 + j];
        out[b * 128 + j] = o;
    }
}

// ---------------------------------------------------------------------------
extern "C" void kernel_launch(void* const* d_in, const int* in_sizes, int n_in,
                              void* d_out, int out_size) {
    const float* u     = (const float*)d_in[0];
    // d_in[1] = x : unused by the reference
    const float* W1    = (const float*)d_in[2];
    const float* b1    = (const float*)d_in[3];
    const float* W2    = (const float*)d_in[4];
    const float* b2    = (const float*)d_in[5];
    const float* embed = (const float*)d_in[6];
    const float* Wq    = (const float*)d_in[7];
    const float* bq    = (const float*)d_in[8];
    const float* Wk    = (const float*)d_in[9];
    const float* bk    = (const float*)d_in[10];
    const float* Wv    = (const float*)d_in[11];
    const float* bv    = (const float*)d_in[12];
    const float* Wo    = (const float*)d_in[13];
    const float* bo    = (const float*)d_in[14];
    float* out = (float*)d_out;

    const size_t smem_bytes = (size_t)SMEM_FLOATS * sizeof(float);  // 208,960 B
    cudaFuncSetAttribute(main_kernel, cudaFuncAttributeMaxDynamicSharedMemorySize,
                         (int)smem_bytes);

    setup_kernel<<<1, 1024>>>(embed, Wq, bq, Wk, bk);
    main_kernel<<<GRID_MAIN, 256, smem_bytes>>>(u, W1, b1, W2, b2);
    epilogue_kernel<<<B_, 128>>>(Wv, bv, Wo, bo, out);
}

// round 5
// speedup vs baseline: 2.7716x; 1.0178x over previous
#include <cuda_runtime.h>

#define B_ 32
#define N_ 4096
#define DU_ 64
#define NTILES 32
#define NTOT (B_ * NTILES)        // 1024 tiles
#define GRID_MAIN 148
#define EPI_BLOCKS 32
#define EPI_RANK0 (GRID_MAIN - EPI_BLOCKS)

// Globals (zero at load; every replay restores them to zero)
__device__ float g_m[B_ * 256];   // moment accumulators [b][h*128+j]
__device__ float g_ab[B_ * 2];    // alpha-sum accumulators
__device__ int   g_tile;          // work ticket counter
__device__ int   g_done;          // blocks finished tile loop
__device__ int   g_done2;         // epilogue blocks finished

__device__ __forceinline__ float tanh_fast(float x) {
    float y;
    asm("tanh.approx.f32 %0, %1;" : "=f"(y) : "f"(x));
    return y;
}
__device__ __forceinline__ float gelu_tanh(float x) {
    const float k0 = 0.7978845608028654f; // sqrt(2/pi)
    float inner = k0 * (x + 0.044715f * x * x * x);
    return 0.5f * x * (1.0f + tanh_fast(inner));
}
__device__ __forceinline__ unsigned f2tf32(float x) {
    unsigned y;
    asm("cvt.rna.tf32.f32 %0, %1;" : "=r"(y) : "f"(x));
    return y;
}
__device__ __forceinline__ float tf32f(float x) { return __uint_as_float(f2tf32(x)); }

__device__ __forceinline__ void mma8(float* c, const unsigned* a, unsigned b0, unsigned b1) {
    asm volatile(
        "mma.sync.aligned.m16n8k8.row.col.f32.tf32.tf32.f32 "
        "{%0,%1,%2,%3}, {%4,%5,%6,%7}, {%8,%9}, {%0,%1,%2,%3};\n"
        : "+f"(c[0]), "+f"(c[1]), "+f"(c[2]), "+f"(c[3])
        : "r"(a[0]), "r"(a[1]), "r"(a[2]), "r"(a[3]), "r"(b0), "r"(b1));
}

// ---------------------------------------------------------------------------
// SMEM layout (floats). B operands live in FRAGMENT ORDER:
//   sB[(wn*KSTEPS + s)*576 + lane*18 + nt*2 + e]
// Per-lane stride 18 words -> LDS.64 banks 18*l mod 32 partition all 32 banks
// per 16-lane phase: conflict-free. A operands: strides 68/132 (= 4 mod 32)
// with lane rows g=0..7 -> 4g+t distinct banks: conflict-free.
// ---------------------------------------------------------------------------
#define OFF_B1   0        // 2 x 8  x 576 = 9216
#define OFF_B2   9216     // 2 x 16 x 576 = 18432 -> 27648
#define OFF_U    27648    // 128 x 68 = 8704 -> 36352
#define OFF_Z1   36352    // 128 x 132 = 16896 -> 53248
#define OFF_WT   53248    // 256 wt + 2 c (+pad) -> 53512
#define OFF_AL   53512    // 256 -> 53768
#define SMEM_FLOATS 53768 // 215,072 bytes
// sZ2 = sm + OFF_U : 128 x 132 fp32 = [27648, 44544) — overlays sU + head of
// sZ1, both dead after the stage-2 k-loop barrier.
// sQ (prologue scratch, 384 floats) also aliases sU.

template<int SA, int KSTEPS>
__device__ __forceinline__ void gemm_fr(const float* __restrict__ A,
                                        const float* __restrict__ Bw,
                                        float acc[2][8][4],
                                        int wm, int g, int t, int lane) {
    unsigned a[2][2][4];
    float2 bp[2][8];
    {   // preload s = 0
        int kk = t;
        #pragma unroll
        for (int mt = 0; mt < 2; mt++) {
            int r = wm * 32 + mt * 16 + g;
            a[0][mt][0] = __float_as_uint(A[r * SA + kk]);
            a[0][mt][1] = __float_as_uint(A[(r + 8) * SA + kk]);
            a[0][mt][2] = __float_as_uint(A[r * SA + kk + 4]);
            a[0][mt][3] = __float_as_uint(A[(r + 8) * SA + kk + 4]);
        }
        const float* bl = Bw + lane * 18;
        #pragma unroll
        for (int nt = 0; nt < 8; nt++) bp[0][nt] = *(const float2*)&bl[nt * 2];
    }
    #pragma unroll
    for (int s = 0; s < KSTEPS; s++) {
        int cur = s & 1, nxt = cur ^ 1;
        if (s + 1 < KSTEPS) {
            int kk = (s + 1) * 8 + t;
            #pragma unroll
            for (int mt = 0; mt < 2; mt++) {
                int r = wm * 32 + mt * 16 + g;
                a[nxt][mt][0] = __float_as_uint(A[r * SA + kk]);
                a[nxt][mt][1] = __float_as_uint(A[(r + 8) * SA + kk]);
                a[nxt][mt][2] = __float_as_uint(A[r * SA + kk + 4]);
                a[nxt][mt][3] = __float_as_uint(A[(r + 8) * SA + kk + 4]);
            }
            const float* bl = Bw + (s + 1) * 576 + lane * 18;
            #pragma unroll
            for (int nt = 0; nt < 8; nt++) bp[nxt][nt] = *(const float2*)&bl[nt * 2];
        }
        #pragma unroll
        for (int nt = 0; nt < 8; nt++) {
            unsigned b0 = __float_as_uint(bp[cur][nt].x);
            unsigned b1 = __float_as_uint(bp[cur][nt].y);
            mma8(acc[0][nt], a[cur][0], b0, b1);
            mma8(acc[1][nt], a[cur][1], b0, b1);
        }
    }
}

// ---------------------------------------------------------------------------
// Single persistent kernel. grid = 148 x 256 threads (8 warps, 4m x 2n tile).
// ---------------------------------------------------------------------------
__global__ __launch_bounds__(256, 1)
void main_kernel(const float* __restrict__ u,
                 const float* __restrict__ W1, const float* __restrict__ b1,
                 const float* __restrict__ W2, const float* __restrict__ b2,
                 const float* __restrict__ embed,
                 const float* __restrict__ Wq, const float* __restrict__ bq,
                 const float* __restrict__ Wk, const float* __restrict__ bk,
                 const float* __restrict__ Wv, const float* __restrict__ bv,
                 const float* __restrict__ Wo, const float* __restrict__ bo,
                 float* __restrict__ out) {
    extern __shared__ float sm[];
    float* sB1 = sm + OFF_B1;
    float* sB2 = sm + OFF_B2;
    float* sU  = sm + OFF_U;
    float* sZ1 = sm + OFF_Z1;
    float* sWT = sm + OFF_WT;
    float* sAl = sm + OFF_AL;
    float* sZ2 = sm + OFF_U;    // alias
    float* sQ  = sm + OFF_U;    // prologue-only alias

    __shared__ int sTileSh;
    __shared__ int sPrev;
    __shared__ float e_m[256], e_ab[2], e_ov[128], e_p[256];

    const int tid = threadIdx.x;
    const int lane = tid & 31, warp = tid >> 5;
    const int wm = warp & 3, wn = warp >> 2;
    const int g = lane >> 2, t = lane & 3;

    // ======== Prologue A: pack W1/W2 into fragment order (tf32) ========
    #pragma unroll 4
    for (int idx = tid; idx < 4096; idx += 256) {          // W1: K=64 -> 8 ksteps
        int nt = idx & 7, ln = (idx >> 3) & 31, s = (idx >> 8) & 7, w = idx >> 11;
        int tt = ln & 3, gg = ln >> 2;
        int n = w * 64 + nt * 8 + gg;
        int k = s * 8 + tt;
        float* d = &sB1[(w * 8 + s) * 576 + ln * 18 + nt * 2];
        d[0] = tf32f(W1[k * 128 + n]);
        d[1] = tf32f(W1[(k + 4) * 128 + n]);
    }
    #pragma unroll 4
    for (int idx = tid; idx < 8192; idx += 256) {          // W2: K=128 -> 16 ksteps
        int nt = idx & 7, ln = (idx >> 3) & 31, s = (idx >> 8) & 15, w = idx >> 12;
        int tt = ln & 3, gg = ln >> 2;
        int n = w * 64 + nt * 8 + gg;
        int k = s * 8 + tt;
        float* d = &sB2[(w * 16 + s) * 576 + ln * 18 + nt * 2];
        d[0] = tf32f(W2[k * 128 + n]);
        d[1] = tf32f(W2[(k + 4) * 128 + n]);
    }

    // ======== Prologue B: q, w~, c (per block; L1-reused) ========
    {
        int j = tid & 127, half = tid >> 7;
        float p = 0.f;
        #pragma unroll 4
        for (int i = half * 64; i < half * 64 + 64; i++) p += embed[i] * Wq[i * 128 + j];
        sQ[half * 128 + j] = p;
    }
    __syncthreads();
    if (tid < 128) sQ[256 + tid] = bq[tid] + sQ[tid] + sQ[128 + tid];
    __syncthreads();
    {
        int h = tid >> 7, i = tid & 127;
        const float* qh = &sQ[256 + h * 64];
        const float* wk = &Wk[i * 128 + h * 64];
        float s0 = 0.f, s1 = 0.f, s2 = 0.f, s3 = 0.f;
        #pragma unroll 8
        for (int d = 0; d < 64; d += 4) {
            s0 += wk[d] * qh[d];     s1 += wk[d + 1] * qh[d + 1];
            s2 += wk[d + 2] * qh[d + 2]; s3 += wk[d + 3] * qh[d + 3];
        }
        sWT[tid] = (s0 + s1) + (s2 + s3);
    }
    if (tid < 2) {
        const float* qh = &sQ[256 + tid * 64];
        const float* bkh = &bk[tid * 64];
        float s = 0.f;
        #pragma unroll 8
        for (int d = 0; d < 64; d++) s += bkh[d] * qh[d];
        sWT[256 + tid] = s;
    }
    // first ticket
    if (tid == 0) sTileSh = atomicAdd(&g_tile, 1);
    __syncthreads();     // sQ dead after this; sWT/c published; ticket visible

    int tile = sTileSh;
    float4 up[8];
    if (tile < NTOT) {
        int bb = tile >> 5, r0 = (tile & 31) * 128;
        const float4* src = (const float4*)(u + ((size_t)bb * N_ + r0) * DU_);
        #pragma unroll
        for (int it = 0; it < 8; it++) up[it] = src[tid + it * 256];
    }

    // ======== Persistent tile loop ========
    while (tile < NTOT) {
        const int b = tile >> 5;

        // stage u (tf32) from prefetched regs
        #pragma unroll
        for (int it = 0; it < 8; it++) {
            int i = tid + it * 256;
            int r = i >> 4, c4 = i & 15;
            float* d = &sU[r * 68 + c4 * 4];
            d[0] = tf32f(up[it].x); d[1] = tf32f(up[it].y);
            d[2] = tf32f(up[it].z); d[3] = tf32f(up[it].w);
        }
        if (tid == 0) sTileSh = atomicAdd(&g_tile, 1);
        __syncthreads();
        int nxt = sTileSh;
        if (nxt < NTOT) {   // prefetch next tile's u during compute
            int bb = nxt >> 5, r0 = (nxt & 31) * 128;
            const float4* src = (const float4*)(u + ((size_t)bb * N_ + r0) * DU_);
            #pragma unroll
            for (int it = 0; it < 8; it++) up[it] = src[tid + it * 256];
        }

        // ---- Stage 1: Z1 = gelu(U @ W1 + b1), K=64 ----
        float acc[2][8][4];
        #pragma unroll
        for (int mt = 0; mt < 2; mt++)
            #pragma unroll
            for (int nt = 0; nt < 8; nt++)
                #pragma unroll
                for (int e = 0; e < 4; e++) acc[mt][nt][e] = 0.f;

        gemm_fr<68, 8>(sU, sB1 + wn * (8 * 576), acc, wm, g, t, lane);

        #pragma unroll
        for (int nt = 0; nt < 8; nt++) {
            int c0 = wn * 64 + nt * 8 + 2 * t;
            float bc0 = __ldg(&b1[c0]), bc1 = __ldg(&b1[c0 + 1]);
            #pragma unroll
            for (int mt = 0; mt < 2; mt++) {
                int r = wm * 32 + mt * 16 + g;
                sZ1[r * 132 + c0]           = tf32f(gelu_tanh(acc[mt][nt][0] + bc0));
                sZ1[r * 132 + c0 + 1]       = tf32f(gelu_tanh(acc[mt][nt][1] + bc1));
                sZ1[(r + 8) * 132 + c0]     = tf32f(gelu_tanh(acc[mt][nt][2] + bc0));
                sZ1[(r + 8) * 132 + c0 + 1] = tf32f(gelu_tanh(acc[mt][nt][3] + bc1));
            }
        }
        __syncthreads();

        // ---- Stage 2: Z2 = gelu(Z1 @ W2 + b2), K=128 ----
        #pragma unroll
        for (int mt = 0; mt < 2; mt++)
            #pragma unroll
            for (int nt = 0; nt < 8; nt++)
                #pragma unroll
                for (int e = 0; e < 4; e++) acc[mt][nt][e] = 0.f;

        gemm_fr<132, 16>(sZ1, sB2 + wn * (16 * 576), acc, wm, g, t, lane);

        __syncthreads();   // sZ1/sU reads done; sZ2 may overwrite them
        #pragma unroll
        for (int nt = 0; nt < 8; nt++) {
            int c0 = wn * 64 + nt * 8 + 2 * t;
            float bc0 = __ldg(&b2[c0]), bc1 = __ldg(&b2[c0 + 1]);
            #pragma unroll
            for (int mt = 0; mt < 2; mt++) {
                int r = wm * 32 + mt * 16 + g;
                sZ2[r * 132 + c0]           = gelu_tanh(acc[mt][nt][0] + bc0);
                sZ2[r * 132 + c0 + 1]       = gelu_tanh(acc[mt][nt][1] + bc1);
                sZ2[(r + 8) * 132 + c0]     = gelu_tanh(acc[mt][nt][2] + bc0);
                sZ2[(r + 8) * 132 + c0 + 1] = gelu_tanh(acc[mt][nt][3] + bc1);
            }
        }
        __syncthreads();

        // ---- Stage 3a: alpha[h][r] ----
        {
            int r = tid & 127, h = tid >> 7;
            const float4* zr = (const float4*)&sZ2[r * 132];
            const float4* wt = (const float4*)&sWT[h * 128];
            float a0 = 0.f, a1 = 0.f, a2 = 0.f, a3 = 0.f;
            #pragma unroll 8
            for (int q4 = 0; q4 < 32; q4++) {
                float4 z = zr[q4], w = wt[q4];
                a0 += z.x * w.x; a1 += z.y * w.y; a2 += z.z * w.z; a3 += z.w * w.w;
            }
            sAl[h * 128 + r] = (a0 + a1) + (a2 + a3) + sWT[256 + h];
        }
        __syncthreads();

        // ---- Stage 3b: moments + abar -> global atomics (spread addrs) ----
        {
            int j = tid & 127, h = tid >> 7;
            const float* al = &sAl[h * 128];
            const float* z = &sZ2[j];
            float m0 = 0.f, m1 = 0.f, m2 = 0.f, m3 = 0.f;
            #pragma unroll 8
            for (int r = 0; r < 128; r += 4) {
                m0 += al[r] * z[r * 132];
                m1 += al[r + 1] * z[(r + 1) * 132];
                m2 += al[r + 2] * z[(r + 2) * 132];
                m3 += al[r + 3] * z[(r + 3) * 132];
            }
            atomicAdd(&g_m[b * 256 + tid], (m0 + m1) + (m2 + m3));
            if (tid < 2) {
                const float* a2p = &sAl[tid * 128];
                float s0 = 0.f, s1 = 0.f, s2 = 0.f, s3 = 0.f;
                #pragma unroll 8
                for (int r = 0; r < 128; r += 4) {
                    s0 += a2p[r]; s1 += a2p[r + 1]; s2 += a2p[r + 2]; s3 += a2p[r + 3];
                }
                atomicAdd(&g_ab[b * 2 + tid], (s0 + s1) + (s2 + s3));
            }
        }
        tile = nxt;
        __syncthreads();   // stage-3 reads of sZ2 done before next STS into sU
    }

    // ======== Exit protocol + distributed epilogue ========
    if (tid == 0) {
        __threadfence();
        sPrev = atomicAdd(&g_done, 1);
    }
    __syncthreads();
    int rank = sPrev;
    if (rank < EPI_RANK0) return;

    if (tid == 0) {
        while (atomicAdd(&g_done, 0) != GRID_MAIN) __nanosleep(64);
    }
    __syncthreads();
    __threadfence();

    int bb = rank - EPI_RANK0;   // 0..31, unique per epilogue block
    e_m[tid] = g_m[bb * 256 + tid];
    if (tid < 2) e_ab[tid] = g_ab[bb * 2 + tid];
    __syncthreads();
    g_m[bb * 256 + tid] = 0.f;          // restore for next replay
    if (tid < 2) g_ab[bb * 2 + tid] = 0.f;

    {   // ov[j] = (abar[h]*bv[j] + m[h][:] . Wv[:,j]) / N
        int j = tid & 127, half = tid >> 7, h = j >> 6;
        float p = 0.f;
        #pragma unroll 4
        for (int pp = half * 64; pp < half * 64 + 64; pp++)
            p += e_m[h * 128 + pp] * __ldg(&Wv[pp * 128 + j]);
        e_p[tid] = p;
    }
    __syncthreads();
    if (tid < 128) {
        int h = tid >> 6;
        e_ov[tid] = (e_p[tid] + e_p[128 + tid] + e_ab[h] * bv[tid]) * (1.0f / N_);
    }
    __syncthreads();
    {   // out[j] = bo[j] + ov . Wo[:,j]
        int j = tid & 127, half = tid >> 7;
        float p = 0.f;
        #pragma unroll 4
        for (int pp = half * 64; pp < half * 64 + 64; pp++)
            p += e_ov[pp] * __ldg(&Wo[pp * 128 + j]);
        e_p[tid] = p;
    }
    __syncthreads();
    if (tid < 128) out[bb * 128 + tid] = e_p[tid] + e_p[128 + tid] + bo[tid];

    if (tid == 0) {
        __threadfence();
        atomicAdd(&g_done2, 1);
        if (rank == GRID_MAIN - 1) {
            while (atomicAdd(&g_done2, 0) != EPI_BLOCKS) __nanosleep(64);
            g_tile = 0; g_done = 0; g_done2 = 0;
        }
    }
}

// ---------------------------------------------------------------------------
extern "C" void kernel_launch(void* const* d_in, const int* in_sizes, int n_in,
                              void* d_out, int out_size) {
    const float* u     = (const float*)d_in[0];
    // d_in[1] = x : unused by the reference
    const float* W1    = (const float*)d_in[2];
    const float* b1    = (const float*)d_in[3];
    const float* W2    = (const float*)d_in[4];
    const float* b2    = (const float*)d_in[5];
    const float* embed = (const float*)d_in[6];
    const float* Wq    = (const float*)d_in[7];
    const float* bq    = (const float*)d_in[8];
    const float* Wk    = (const float*)d_in[9];
    const float* bk    = (const float*)d_in[10];
    const float* Wv    = (const float*)d_in[11];
    const float* bv    = (const float*)d_in[12];
    const float* Wo    = (const float*)d_in[13];
    const float* bo    = (const float*)d_in[14];
    float* out = (float*)d_out;

    const size_t smem_bytes = (size_t)SMEM_FLOATS * sizeof(float);  // 215,072 B
    cudaFuncSetAttribute(main_kernel, cudaFuncAttributeMaxDynamicSharedMemorySize,
                         (int)smem_bytes);

    main_kernel<<<GRID_MAIN, 256, smem_bytes>>>(
        u, W1, b1, W2, b2, embed, Wq, bq, Wk, bk, Wv, bv, Wo, bo, out);
}

// round 6
// speedup vs baseline: 2.9047x; 1.0480x over previous
#include <cuda_runtime.h>

#define B_ 32
#define N_ 4096
#define DU_ 64
#define NTILES 32
#define NTOT (B_ * NTILES)        // 1024 tiles
#define GRID_MAIN 148
#define EPI_BLOCKS 32
#define EPI_RANK0 (GRID_MAIN - EPI_BLOCKS)

// Globals (zero at load; every replay restores them to zero)
__device__ float g_m[B_ * 256];   // moment accumulators [b][h*128+j]
__device__ float g_ab[B_ * 2];    // alpha-sum accumulators
__device__ int   g_tile;          // work ticket counter
__device__ int   g_done;          // blocks finished tile loop
__device__ int   g_done2;         // epilogue blocks finished

__device__ __forceinline__ float tanh_fast(float x) {
    float y;
    asm("tanh.approx.f32 %0, %1;" : "=f"(y) : "f"(x));
    return y;
}
__device__ __forceinline__ float gelu_tanh(float x) {
    const float k0 = 0.7978845608028654f; // sqrt(2/pi)
    float inner = k0 * (x + 0.044715f * x * x * x);
    return 0.5f * x * (1.0f + tanh_fast(inner));
}
__device__ __forceinline__ unsigned f2tf32(float x) {
    unsigned y;
    asm("cvt.rna.tf32.f32 %0, %1;" : "=r"(y) : "f"(x));
    return y;
}
__device__ __forceinline__ float tf32f(float x) { return __uint_as_float(f2tf32(x)); }

__device__ __forceinline__ void mma8(float* c, const unsigned* a, unsigned b0, unsigned b1) {
    asm volatile(
        "mma.sync.aligned.m16n8k8.row.col.f32.tf32.tf32.f32 "
        "{%0,%1,%2,%3}, {%4,%5,%6,%7}, {%8,%9}, {%0,%1,%2,%3};\n"
        : "+f"(c[0]), "+f"(c[1]), "+f"(c[2]), "+f"(c[3])
        : "r"(a[0]), "r"(a[1]), "r"(a[2]), "r"(a[3]), "r"(b0), "r"(b1));
}

// ---------------------------------------------------------------------------
// SMEM layout (floats). B operands in FRAGMENT ORDER, stride 8 + XOR swizzle:
//   sB[(wn*KSTEPS + s)*256 + lane*8 + ((nt ^ ((lane>>2)&3)) * 2) + e]
// LDS.64 bank check: lanes sharing 8*l mod 32 (l, l+4, l+8, l+12) have
// (l>>2)&3 = 0,1,2,3 -> granule offsets {0,2,4,6} distinct -> conflict-free.
// A operands: strides 68/132 (= 4 mod 32), lane addr 4g+t distinct: conflict-free.
// ---------------------------------------------------------------------------
#define OFF_B1   0        // 4 x 8  x 256 = 8192
#define OFF_B2   8192     // 4 x 16 x 256 = 16384 -> 24576
#define OFF_U    24576    // 128 x 68 = 8704 -> 33280
#define OFF_Z1   33280    // 128 x 132 = 16896 -> 50176
#define OFF_WT   50176    // 256 wt + 2 c (+pad 6) -> 50440
#define OFF_AL   50440    // 256 -> 50696
#define OFF_SCR  50696    // 512 -> 51208
#define SMEM_FLOATS 51208 // 204,832 bytes
// sZ2 = sm + OFF_U : 128 x 132 fp32 — overlays sU + head of sZ1 (both dead
// after the stage-2 k-loop barrier). sQ (prologue, 384 floats) aliases sU.

template<int SA, int KSTEPS>
__device__ __forceinline__ void gemm_fr(const float* __restrict__ A,
                                        const float* __restrict__ Bw,
                                        float acc[2][4][4],
                                        int wm, int g, int t, int lane, int xv) {
    unsigned a[2][2][4];
    float2 bp[2][4];
    {   // preload kstep 0
        #pragma unroll
        for (int mt = 0; mt < 2; mt++) {
            int r = wm * 32 + mt * 16 + g;
            a[0][mt][0] = __float_as_uint(A[r * SA + t]);
            a[0][mt][1] = __float_as_uint(A[(r + 8) * SA + t]);
            a[0][mt][2] = __float_as_uint(A[r * SA + t + 4]);
            a[0][mt][3] = __float_as_uint(A[(r + 8) * SA + t + 4]);
        }
        const float* bl = Bw + lane * 8;
        #pragma unroll
        for (int nt = 0; nt < 4; nt++) bp[0][nt] = *(const float2*)&bl[(nt ^ xv) * 2];
    }
    #pragma unroll
    for (int s = 0; s < KSTEPS; s++) {
        int cur = s & 1, nxt = cur ^ 1;
        if (s + 1 < KSTEPS) {
            int kk = (s + 1) * 8 + t;
            #pragma unroll
            for (int mt = 0; mt < 2; mt++) {
                int r = wm * 32 + mt * 16 + g;
                a[nxt][mt][0] = __float_as_uint(A[r * SA + kk]);
                a[nxt][mt][1] = __float_as_uint(A[(r + 8) * SA + kk]);
                a[nxt][mt][2] = __float_as_uint(A[r * SA + kk + 4]);
                a[nxt][mt][3] = __float_as_uint(A[(r + 8) * SA + kk + 4]);
            }
            const float* bl = Bw + (s + 1) * 256 + lane * 8;
            #pragma unroll
            for (int nt = 0; nt < 4; nt++) bp[nxt][nt] = *(const float2*)&bl[(nt ^ xv) * 2];
        }
        #pragma unroll
        for (int nt = 0; nt < 4; nt++) {
            unsigned b0 = __float_as_uint(bp[cur][nt].x);
            unsigned b1 = __float_as_uint(bp[cur][nt].y);
            mma8(acc[0][nt], a[cur][0], b0, b1);
            mma8(acc[1][nt], a[cur][1], b0, b1);
        }
    }
}

// ---------------------------------------------------------------------------
// Single persistent kernel. grid = 148 x 512 threads (16 warps, 4m x 4n).
// ---------------------------------------------------------------------------
__global__ __launch_bounds__(512, 1)
void main_kernel(const float* __restrict__ u,
                 const float* __restrict__ W1, const float* __restrict__ b1,
                 const float* __restrict__ W2, const float* __restrict__ b2,
                 const float* __restrict__ embed,
                 const float* __restrict__ Wq, const float* __restrict__ bq,
                 const float* __restrict__ Wk, const float* __restrict__ bk,
                 const float* __restrict__ Wv, const float* __restrict__ bv,
                 const float* __restrict__ Wo, const float* __restrict__ bo,
                 float* __restrict__ out) {
    extern __shared__ float sm[];
    float* sB1 = sm + OFF_B1;
    float* sB2 = sm + OFF_B2;
    float* sU  = sm + OFF_U;
    float* sZ1 = sm + OFF_Z1;
    float* sWT = sm + OFF_WT;
    float* sAl = sm + OFF_AL;
    float* sScr = sm + OFF_SCR;
    float* sZ2 = sm + OFF_U;    // alias
    float* sQ  = sm + OFF_U;    // prologue-only alias

    __shared__ int sTileSh;
    __shared__ int sPrev;
    __shared__ float e_m[256], e_ab[2], e_ov[128], e_p[512];

    const int tid = threadIdx.x;
    const int lane = tid & 31, warp = tid >> 5;
    const int wm = warp & 3, wn = warp >> 2;   // 4m x 4n
    const int g = lane >> 2, t = lane & 3;
    const int xv = (lane >> 2) & 3;

    // ======== Prologue A: pack W1/W2 into fragment order (tf32, swizzled) ====
    #pragma unroll 2
    for (int idx = tid; idx < 4096; idx += 512) {   // W1: 4w x 8s x 32l x 4nt
        int nt = idx & 3, ln = (idx >> 2) & 31, s = (idx >> 7) & 7, w = idx >> 10;
        int tt = ln & 3, gg = ln >> 2;
        int n = w * 32 + nt * 8 + gg;
        int k = s * 8 + tt;
        float* d = &sB1[(w * 8 + s) * 256 + ln * 8 + ((nt ^ (gg & 3)) * 2)];
        d[0] = tf32f(W1[k * 128 + n]);
        d[1] = tf32f(W1[(k + 4) * 128 + n]);
    }
    #pragma unroll 2
    for (int idx = tid; idx < 8192; idx += 512) {   // W2: 4w x 16s x 32l x 4nt
        int nt = idx & 3, ln = (idx >> 2) & 31, s = (idx >> 7) & 15, w = idx >> 11;
        int tt = ln & 3, gg = ln >> 2;
        int n = w * 32 + nt * 8 + gg;
        int k = s * 8 + tt;
        float* d = &sB2[(w * 16 + s) * 256 + ln * 8 + ((nt ^ (gg & 3)) * 2)];
        d[0] = tf32f(W2[k * 128 + n]);
        d[1] = tf32f(W2[(k + 4) * 128 + n]);
    }

    // ======== Prologue B: q, w~, c ========
    if (tid < 256) {
        int j = tid & 127, half = tid >> 7;
        float p = 0.f;
        #pragma unroll 4
        for (int i = half * 64; i < half * 64 + 64; i++) p += embed[i] * Wq[i * 128 + j];
        sQ[half * 128 + j] = p;
    }
    __syncthreads();
    if (tid < 128) sQ[256 + tid] = bq[tid] + sQ[tid] + sQ[128 + tid];
    __syncthreads();
    if (tid < 256) {
        int h = tid >> 7, i = tid & 127;
        const float* qh = &sQ[256 + h * 64];
        const float* wk = &Wk[i * 128 + h * 64];
        float s0 = 0.f, s1 = 0.f, s2 = 0.f, s3 = 0.f;
        #pragma unroll 8
        for (int d = 0; d < 64; d += 4) {
            s0 += wk[d] * qh[d];         s1 += wk[d + 1] * qh[d + 1];
            s2 += wk[d + 2] * qh[d + 2]; s3 += wk[d + 3] * qh[d + 3];
        }
        sWT[tid] = (s0 + s1) + (s2 + s3);
    }
    if (tid < 2) {
        const float* qh = &sQ[256 + tid * 64];
        const float* bkh = &bk[tid * 64];
        float s = 0.f;
        #pragma unroll 8
        for (int d = 0; d < 64; d++) s += bkh[d] * qh[d];
        sWT[256 + tid] = s;
    }
    if (tid == 0) sTileSh = atomicAdd(&g_tile, 1);
    __syncthreads();     // sQ dead; sWT published; ticket visible
    int tile = sTileSh;

    // ======== Persistent tile loop ========
    while (tile < NTOT) {
        const int b = tile >> 5;
        const int row0 = (tile & 31) * 128;

        // stage u (tf32): 512 threads x 4 float4
        {
            const float4* src = (const float4*)(u + ((size_t)b * N_ + row0) * DU_);
            #pragma unroll
            for (int it = 0; it < 4; it++) {
                int i = tid + it * 512;
                int r = i >> 4, c4 = i & 15;
                float4 v = src[i];
                float* d = &sU[r * 68 + c4 * 4];
                d[0] = tf32f(v.x); d[1] = tf32f(v.y);
                d[2] = tf32f(v.z); d[3] = tf32f(v.w);
            }
        }
        if (tid == 0) sTileSh = atomicAdd(&g_tile, 1);
        __syncthreads();
        int nxt = sTileSh;

        // ---- Stage 1: Z1 = gelu(U @ W1 + b1), K=64 ----
        float acc[2][4][4];
        #pragma unroll
        for (int mt = 0; mt < 2; mt++)
            #pragma unroll
            for (int nt = 0; nt < 4; nt++)
                #pragma unroll
                for (int e = 0; e < 4; e++) acc[mt][nt][e] = 0.f;

        gemm_fr<68, 8>(sU, sB1 + wn * (8 * 256), acc, wm, g, t, lane, xv);

        #pragma unroll
        for (int nt = 0; nt < 4; nt++) {
            int c0 = wn * 32 + nt * 8 + 2 * t;
            float bc0 = __ldg(&b1[c0]), bc1 = __ldg(&b1[c0 + 1]);
            #pragma unroll
            for (int mt = 0; mt < 2; mt++) {
                int r = wm * 32 + mt * 16 + g;
                sZ1[r * 132 + c0]           = tf32f(gelu_tanh(acc[mt][nt][0] + bc0));
                sZ1[r * 132 + c0 + 1]       = tf32f(gelu_tanh(acc[mt][nt][1] + bc1));
                sZ1[(r + 8) * 132 + c0]     = tf32f(gelu_tanh(acc[mt][nt][2] + bc0));
                sZ1[(r + 8) * 132 + c0 + 1] = tf32f(gelu_tanh(acc[mt][nt][3] + bc1));
            }
        }
        __syncthreads();

        // ---- Stage 2: Z2 = gelu(Z1 @ W2 + b2), K=128 ----
        #pragma unroll
        for (int mt = 0; mt < 2; mt++)
            #pragma unroll
            for (int nt = 0; nt < 4; nt++)
                #pragma unroll
                for (int e = 0; e < 4; e++) acc[mt][nt][e] = 0.f;

        gemm_fr<132, 16>(sZ1, sB2 + wn * (16 * 256), acc, wm, g, t, lane, xv);

        __syncthreads();   // sZ1/sU reads done; sZ2 may overwrite
        #pragma unroll
        for (int nt = 0; nt < 4; nt++) {
            int c0 = wn * 32 + nt * 8 + 2 * t;
            float bc0 = __ldg(&b2[c0]), bc1 = __ldg(&b2[c0 + 1]);
            #pragma unroll
            for (int mt = 0; mt < 2; mt++) {
                int r = wm * 32 + mt * 16 + g;
                sZ2[r * 132 + c0]           = gelu_tanh(acc[mt][nt][0] + bc0);
                sZ2[r * 132 + c0 + 1]       = gelu_tanh(acc[mt][nt][1] + bc1);
                sZ2[(r + 8) * 132 + c0]     = gelu_tanh(acc[mt][nt][2] + bc0);
                sZ2[(r + 8) * 132 + c0 + 1] = gelu_tanh(acc[mt][nt][3] + bc1);
            }
        }
        __syncthreads();

        // ---- Stage 3a: alpha[h][r], split over j-halves ----
        {
            int half = tid >> 8, task = tid & 255;
            int r = task & 127, h = task >> 7;
            const float4* zr = (const float4*)&sZ2[r * 132 + half * 64];
            const float4* wt = (const float4*)&sWT[h * 128 + half * 64];
            float a0 = 0.f, a1 = 0.f, a2 = 0.f, a3 = 0.f;
            #pragma unroll 4
            for (int q4 = 0; q4 < 16; q4++) {
                float4 z = zr[q4], w = wt[q4];
                a0 += z.x * w.x; a1 += z.y * w.y; a2 += z.z * w.z; a3 += z.w * w.w;
            }
            sScr[half * 256 + task] = (a0 + a1) + (a2 + a3);
        }
        __syncthreads();
        if (tid < 256)
            sAl[tid] = sScr[tid] + sScr[256 + tid] + sWT[256 + (tid >> 7)];
        __syncthreads();

        // ---- Stage 3b: moments, split over r-halves ----
        {
            int half = tid >> 8, task = tid & 255;
            int j = task & 127, h = task >> 7;
            const float* al = &sAl[h * 128 + half * 64];
            const float* z = &sZ2[j + half * 64 * 132];
            float m0 = 0.f, m1 = 0.f, m2 = 0.f, m3 = 0.f;
            #pragma unroll 4
            for (int r = 0; r < 64; r += 4) {
                m0 += al[r] * z[r * 132];
                m1 += al[r + 1] * z[(r + 1) * 132];
                m2 += al[r + 2] * z[(r + 2) * 132];
                m3 += al[r + 3] * z[(r + 3) * 132];
            }
            sScr[half * 256 + task] = (m0 + m1) + (m2 + m3);
        }
        __syncthreads();
        if (tid < 256)
            atomicAdd(&g_m[b * 256 + tid], sScr[tid] + sScr[256 + tid]);
        if (tid < 2) {
            const float* a2p = &sAl[tid * 128];
            float s0 = 0.f, s1 = 0.f, s2 = 0.f, s3 = 0.f;
            #pragma unroll 8
            for (int r = 0; r < 128; r += 4) {
                s0 += a2p[r]; s1 += a2p[r + 1]; s2 += a2p[r + 2]; s3 += a2p[r + 3];
            }
            atomicAdd(&g_ab[b * 2 + tid], (s0 + s1) + (s2 + s3));
        }
        tile = nxt;
        __syncthreads();   // stage-3 reads of sZ2/sAl done before next staging
    }

    // ======== Exit protocol + distributed epilogue ========
    if (tid == 0) {
        __threadfence();
        sPrev = atomicAdd(&g_done, 1);
    }
    __syncthreads();
    int rank = sPrev;
    if (rank < EPI_RANK0) return;

    if (tid == 0) {
        while (atomicAdd(&g_done, 0) != GRID_MAIN) __nanosleep(64);
    }
    __syncthreads();
    __threadfence();

    int bb = rank - EPI_RANK0;   // 0..31, unique per epilogue block
    if (tid < 256) e_m[tid] = g_m[bb * 256 + tid];
    if (tid < 2) e_ab[tid] = g_ab[bb * 2 + tid];
    __syncthreads();
    if (tid < 256) g_m[bb * 256 + tid] = 0.f;   // restore for next replay
    if (tid < 2) g_ab[bb * 2 + tid] = 0.f;

    {   // ov[j] = (abar[h]*bv[j] + m[h][:] . Wv[:,j]) / N  (4-way split over p)
        int j = tid & 127, q = tid >> 7, h = j >> 6;
        float p = 0.f;
        #pragma unroll 4
        for (int pp = q * 32; pp < q * 32 + 32; pp++)
            p += e_m[h * 128 + pp] * __ldg(&Wv[pp * 128 + j]);
        e_p[tid] = p;
    }
    __syncthreads();
    if (tid < 128) {
        int h = tid >> 6;
        e_ov[tid] = (e_p[tid] + e_p[128 + tid] + e_p[256 + tid] + e_p[384 + tid]
                     + e_ab[h] * bv[tid]) * (1.0f / N_);
    }
    __syncthreads();
    {   // out[j] = bo[j] + ov . Wo[:,j]
        int j = tid & 127, q = tid >> 7;
        float p = 0.f;
        #pragma unroll 4
        for (int pp = q * 32; pp < q * 32 + 32; pp++)
            p += e_ov[pp] * __ldg(&Wo[pp * 128 + j]);
        e_p[tid] = p;
    }
    __syncthreads();
    if (tid < 128)
        out[bb * 128 + tid] = e_p[tid] + e_p[128 + tid] + e_p[256 + tid]
                              + e_p[384 + tid] + bo[tid];

    if (tid == 0) {
        __threadfence();
        atomicAdd(&g_done2, 1);
        if (rank == GRID_MAIN - 1) {
            while (atomicAdd(&g_done2, 0) != EPI_BLOCKS) __nanosleep(64);
            g_tile = 0; g_done = 0; g_done2 = 0;
        }
    }
}

// ---------------------------------------------------------------------------
extern "C" void kernel_launch(void* const* d_in, const int* in_sizes, int n_in,
                              void* d_out, int out_size) {
    const float* u     = (const float*)d_in[0];
    // d_in[1] = x : unused by the reference
    const float* W1    = (const float*)d_in[2];
    const float* b1    = (const float*)d_in[3];
    const float* W2    = (const float*)d_in[4];
    const float* b2    = (const float*)d_in[5];
    const float* embed = (const float*)d_in[6];
    const float* Wq    = (const float*)d_in[7];
    const float* bq    = (const float*)d_in[8];
    const float* Wk    = (const float*)d_in[9];
    const float* bk    = (const float*)d_in[10];
    const float* Wv    = (const float*)d_in[11];
    const float* bv    = (const float*)d_in[12];
    const float* Wo    = (const float*)d_in[13];
    const float* bo    = (const float*)d_in[14];
    float* out = (float*)d_out;

    const size_t smem_bytes = (size_t)SMEM_FLOATS * sizeof(float);  // 204,832 B
    cudaFuncSetAttribute(main_kernel, cudaFuncAttributeMaxDynamicSharedMemorySize,
                         (int)smem_bytes);

    main_kernel<<<GRID_MAIN, 512, smem_bytes>>>(
        u, W1, b1, W2, b2, embed, Wq, bq, Wk, bk, Wv, bv, Wo, bo, out);
}

// round 8
// speedup vs baseline: 2.9703x; 1.0226x over previous
#include <cuda_runtime.h>

#define B_ 32
#define N_ 4096
#define DU_ 64
#define NTILES 32
#define NTOT (B_ * NTILES)        // 1024 tiles
#define GRID_MAIN 148
#define EPI_BLOCKS 32
#define EPI_RANK0 (GRID_MAIN - EPI_BLOCKS)

// Globals (zero at load; every replay restores them to zero)
__device__ float g_m[B_ * 256];   // moment accumulators [b][h*128+j]
__device__ float g_ab[B_ * 2];    // alpha-sum accumulators
__device__ int   g_tile;          // work ticket counter
__device__ int   g_done;          // blocks finished tile loop
__device__ int   g_done2;         // epilogue blocks finished

__device__ __forceinline__ float tanh_fast(float x) {
    float y;
    asm("tanh.approx.f32 %0, %1;" : "=f"(y) : "f"(x));
    return y;
}
__device__ __forceinline__ float gelu_tanh(float x) {
    const float k0 = 0.7978845608028654f; // sqrt(2/pi)
    float inner = k0 * (x + 0.044715f * x * x * x);
    return 0.5f * x * (1.0f + tanh_fast(inner));
}
__device__ __forceinline__ unsigned f2tf32(float x) {
    unsigned y;
    asm("cvt.rna.tf32.f32 %0, %1;" : "=r"(y) : "f"(x));
    return y;
}
__device__ __forceinline__ float tf32f(float x) { return __uint_as_float(f2tf32(x)); }

__device__ __forceinline__ void mma8(float* c, const unsigned* a, unsigned b0, unsigned b1) {
    asm volatile(
        "mma.sync.aligned.m16n8k8.row.col.f32.tf32.tf32.f32 "
        "{%0,%1,%2,%3}, {%4,%5,%6,%7}, {%8,%9}, {%0,%1,%2,%3};\n"
        : "+f"(c[0]), "+f"(c[1]), "+f"(c[2]), "+f"(c[3])
        : "r"(a[0]), "r"(a[1]), "r"(a[2]), "r"(a[3]), "r"(b0), "r"(b1));
}

// ---------------------------------------------------------------------------
// SMEM layout (floats). B operands in FRAGMENT ORDER, stride 8 + XOR swizzle
// (conflict-free LDS.64). A operands: strides 68/132 (= 4 mod 32),
// lane addr 4g+t all distinct: conflict-free.
// sAp: alpha partials [row][12] (stride 12 -> banks 12g distinct, float2-aligned).
// ---------------------------------------------------------------------------
#define OFF_B1   0        // 4 x 8  x 256 = 8192
#define OFF_B2   8192     // 4 x 16 x 256 = 16384 -> 24576
#define OFF_U    24576    // 128 x 68 = 8704 -> 33280  (tf32, RN-rounded)
#define OFF_Z1   33280    // 128 x 132 = 16896 -> 50176
#define OFF_WT   50176    // 256 wt + 2 c (+pad 6) -> 50440
#define OFF_AP   50440    // 128 x 12 = 1536 -> 51976
#define SMEM_FLOATS 51976 // 207,904 bytes
// sQ (prologue scratch, 384 floats) aliases sU.

template<int SA, int KSTEPS>
__device__ __forceinline__ void gemm_fr(const float* __restrict__ A,
                                        const float* __restrict__ Bw,
                                        float acc[2][4][4],
                                        int wm, int g, int t, int lane, int xv) {
    unsigned a[2][2][4];
    float2 bp[2][4];
    {   // preload kstep 0
        #pragma unroll
        for (int mt = 0; mt < 2; mt++) {
            int r = wm * 32 + mt * 16 + g;
            a[0][mt][0] = __float_as_uint(A[r * SA + t]);
            a[0][mt][1] = __float_as_uint(A[(r + 8) * SA + t]);
            a[0][mt][2] = __float_as_uint(A[r * SA + t + 4]);
            a[0][mt][3] = __float_as_uint(A[(r + 8) * SA + t + 4]);
        }
        const float* bl = Bw + lane * 8;
        #pragma unroll
        for (int nt = 0; nt < 4; nt++) bp[0][nt] = *(const float2*)&bl[(nt ^ xv) * 2];
    }
    #pragma unroll
    for (int s = 0; s < KSTEPS; s++) {
        int cur = s & 1, nxt = cur ^ 1;
        if (s + 1 < KSTEPS) {
            int kk = (s + 1) * 8 + t;
            #pragma unroll
            for (int mt = 0; mt < 2; mt++) {
                int r = wm * 32 + mt * 16 + g;
                a[nxt][mt][0] = __float_as_uint(A[r * SA + kk]);
                a[nxt][mt][1] = __float_as_uint(A[(r + 8) * SA + kk]);
                a[nxt][mt][2] = __float_as_uint(A[r * SA + kk + 4]);
                a[nxt][mt][3] = __float_as_uint(A[(r + 8) * SA + kk + 4]);
            }
            const float* bl = Bw + (s + 1) * 256 + lane * 8;
            #pragma unroll
            for (int nt = 0; nt < 4; nt++) bp[nxt][nt] = *(const float2*)&bl[(nt ^ xv) * 2];
        }
        #pragma unroll
        for (int nt = 0; nt < 4; nt++) {
            unsigned b0 = __float_as_uint(bp[cur][nt].x);
            unsigned b1 = __float_as_uint(bp[cur][nt].y);
            mma8(acc[0][nt], a[cur][0], b0, b1);
            mma8(acc[1][nt], a[cur][1], b0, b1);
        }
    }
}

// ---------------------------------------------------------------------------
// Single persistent kernel. grid = 148 x 512 threads (16 warps, 4m x 4n).
// 3 block barriers per tile; u prefetched via registers (RN tf32 on STS).
// ---------------------------------------------------------------------------
__global__ __launch_bounds__(512, 1)
void main_kernel(const float* __restrict__ u,
                 const float* __restrict__ W1, const float* __restrict__ b1,
                 const float* __restrict__ W2, const float* __restrict__ b2,
                 const float* __restrict__ embed,
                 const float* __restrict__ Wq, const float* __restrict__ bq,
                 const float* __restrict__ Wk, const float* __restrict__ bk,
                 const float* __restrict__ Wv, const float* __restrict__ bv,
                 const float* __restrict__ Wo, const float* __restrict__ bo,
                 float* __restrict__ out) {
    extern __shared__ float sm[];
    float* sB1 = sm + OFF_B1;
    float* sB2 = sm + OFF_B2;
    float* sU  = sm + OFF_U;
    float* sZ1 = sm + OFF_Z1;
    float* sWT = sm + OFF_WT;
    float* sAp = sm + OFF_AP;
    float* sQ  = sm + OFF_U;    // prologue-only alias

    __shared__ int sTileSh;
    __shared__ int sPrev;
    __shared__ float e_m[256], e_ab[2], e_ov[128], e_p[512];

    const int tid = threadIdx.x;
    const int lane = tid & 31, warp = tid >> 5;
    const int wm = warp & 3, wn = warp >> 2;   // 4m x 4n
    const int g = lane >> 2, t = lane & 3;
    const int xv = g & 3;

    // ======== Prologue A: pack W1/W2 into fragment order (tf32, swizzled) ====
    #pragma unroll 2
    for (int idx = tid; idx < 4096; idx += 512) {   // W1: 4w x 8s x 32l x 4nt
        int nt = idx & 3, ln = (idx >> 2) & 31, s = (idx >> 7) & 7, w = idx >> 10;
        int tt = ln & 3, gg = ln >> 2;
        int n = w * 32 + nt * 8 + gg;
        int k = s * 8 + tt;
        float* d = &sB1[(w * 8 + s) * 256 + ln * 8 + ((nt ^ (gg & 3)) * 2)];
        d[0] = tf32f(W1[k * 128 + n]);
        d[1] = tf32f(W1[(k + 4) * 128 + n]);
    }
    #pragma unroll 2
    for (int idx = tid; idx < 8192; idx += 512) {   // W2: 4w x 16s x 32l x 4nt
        int nt = idx & 3, ln = (idx >> 2) & 31, s = (idx >> 7) & 15, w = idx >> 11;
        int tt = ln & 3, gg = ln >> 2;
        int n = w * 32 + nt * 8 + gg;
        int k = s * 8 + tt;
        float* d = &sB2[(w * 16 + s) * 256 + ln * 8 + ((nt ^ (gg & 3)) * 2)];
        d[0] = tf32f(W2[k * 128 + n]);
        d[1] = tf32f(W2[(k + 4) * 128 + n]);
    }

    // ======== Prologue B: q, w~, c ========
    if (tid < 256) {
        int j = tid & 127, half = tid >> 7;
        float p = 0.f;
        #pragma unroll 4
        for (int i = half * 64; i < half * 64 + 64; i++) p += embed[i] * Wq[i * 128 + j];
        sQ[half * 128 + j] = p;
    }
    __syncthreads();
    if (tid < 128) sQ[256 + tid] = bq[tid] + sQ[tid] + sQ[128 + tid];
    __syncthreads();
    if (tid < 256) {
        int h = tid >> 7, i = tid & 127;
        const float* qh = &sQ[256 + h * 64];
        const float* wk = &Wk[i * 128 + h * 64];
        float s0 = 0.f, s1 = 0.f, s2 = 0.f, s3 = 0.f;
        #pragma unroll 8
        for (int d = 0; d < 64; d += 4) {
            s0 += wk[d] * qh[d];         s1 += wk[d + 1] * qh[d + 1];
            s2 += wk[d + 2] * qh[d + 2]; s3 += wk[d + 3] * qh[d + 3];
        }
        sWT[tid] = (s0 + s1) + (s2 + s3);
    }
    if (tid < 2) {
        const float* qh = &sQ[256 + tid * 64];
        const float* bkh = &bk[tid * 64];
        float s = 0.f;
        #pragma unroll 8
        for (int d = 0; d < 64; d++) s += bkh[d] * qh[d];
        sWT[256 + tid] = s;
    }
    if (tid == 0) sTileSh = atomicAdd(&g_tile, 1);
    __syncthreads();    // sQ dead; sWT + first ticket visible

    int tile = sTileSh;

    // persistent per-thread constants: wt pairs for my 8 cols, c values
    float2 wtp[2][4];   // [h][nt] at cols (wn*32+nt*8+2t, +1)
    #pragma unroll
    for (int h = 0; h < 2; h++)
        #pragma unroll
        for (int nt = 0; nt < 4; nt++)
            wtp[h][nt] = *(const float2*)&sWT[h * 128 + wn * 32 + nt * 8 + 2 * t];
    const float cc0 = sWT[256], cc1 = sWT[257];

    // prefetch first u tile into registers
    float4 up[4];
    if (tile < NTOT) {
        int bb = tile >> 5, r0 = (tile & 31) * 128;
        const float4* src = (const float4*)(u + ((size_t)bb * N_ + r0) * DU_);
        #pragma unroll
        for (int it = 0; it < 4; it++) up[it] = src[tid + it * 512];
    }
    if (tid == 0) sTileSh = atomicAdd(&g_tile, 1);
    __syncthreads();    // second ticket visible; sQ region now reusable as sU
    int nxt = sTileSh;

    // ======== Persistent tile loop (3 barriers) ========
    while (tile < NTOT) {
        // stage u (RN tf32) from prefetched regs
        #pragma unroll
        for (int it = 0; it < 4; it++) {
            int i = tid + it * 512;
            int r = i >> 4, c4 = i & 15;
            float* d = &sU[r * 68 + c4 * 4];
            d[0] = tf32f(up[it].x); d[1] = tf32f(up[it].y);
            d[2] = tf32f(up[it].z); d[3] = tf32f(up[it].w);
        }
        __syncthreads();                      // bar0: sU visible

        // ---- Stage 1: Z1 = gelu(U @ W1 + b1), K=64 ----
        float acc[2][4][4];
        #pragma unroll
        for (int mt = 0; mt < 2; mt++)
            #pragma unroll
            for (int nt = 0; nt < 4; nt++)
                #pragma unroll
                for (int e = 0; e < 4; e++) acc[mt][nt][e] = 0.f;

        gemm_fr<68, 8>(sU, sB1 + wn * (8 * 256), acc, wm, g, t, lane, xv);

        if (tid == 0) sTileSh = atomicAdd(&g_tile, 1);

        #pragma unroll
        for (int nt = 0; nt < 4; nt++) {
            int c0 = wn * 32 + nt * 8 + 2 * t;
            float bc0 = __ldg(&b1[c0]), bc1 = __ldg(&b1[c0 + 1]);
            #pragma unroll
            for (int mt = 0; mt < 2; mt++) {
                int r = wm * 32 + mt * 16 + g;
                sZ1[r * 132 + c0]           = tf32f(gelu_tanh(acc[mt][nt][0] + bc0));
                sZ1[r * 132 + c0 + 1]       = tf32f(gelu_tanh(acc[mt][nt][1] + bc1));
                sZ1[(r + 8) * 132 + c0]     = tf32f(gelu_tanh(acc[mt][nt][2] + bc0));
                sZ1[(r + 8) * 132 + c0 + 1] = tf32f(gelu_tanh(acc[mt][nt][3] + bc1));
            }
        }
        __syncthreads();                      // bar_a: sZ1 + next ticket visible
        int nxt2 = sTileSh;

        // prefetch u(nxt) into registers; LDG latency hides behind gemm2
        if (nxt < NTOT) {
            int bb = nxt >> 5, r0 = (nxt & 31) * 128;
            const float4* src = (const float4*)(u + ((size_t)bb * N_ + r0) * DU_);
            #pragma unroll
            for (int it = 0; it < 4; it++) up[it] = src[tid + it * 512];
        }

        // ---- Stage 2: Z2 = gelu(Z1 @ W2 + b2), K=128 (stays in registers) ----
        #pragma unroll
        for (int mt = 0; mt < 2; mt++)
            #pragma unroll
            for (int nt = 0; nt < 4; nt++)
                #pragma unroll
                for (int e = 0; e < 4; e++) acc[mt][nt][e] = 0.f;

        gemm_fr<132, 16>(sZ1, sB2 + wn * (16 * 256), acc, wm, g, t, lane, xv);

        #pragma unroll
        for (int nt = 0; nt < 4; nt++) {
            int c0 = wn * 32 + nt * 8 + 2 * t;
            float bc0 = __ldg(&b2[c0]), bc1 = __ldg(&b2[c0 + 1]);
            acc[0][nt][0] = gelu_tanh(acc[0][nt][0] + bc0);
            acc[0][nt][1] = gelu_tanh(acc[0][nt][1] + bc1);
            acc[0][nt][2] = gelu_tanh(acc[0][nt][2] + bc0);
            acc[0][nt][3] = gelu_tanh(acc[0][nt][3] + bc1);
            acc[1][nt][0] = gelu_tanh(acc[1][nt][0] + bc0);
            acc[1][nt][1] = gelu_tanh(acc[1][nt][1] + bc1);
            acc[1][nt][2] = gelu_tanh(acc[1][nt][2] + bc0);
            acc[1][nt][3] = gelu_tanh(acc[1][nt][3] + bc1);
        }

        // ---- alpha partials over this warp's 32 cols; reduce over t-lanes ----
        {
            float pa[2][2][2];   // [mt][p][h]
            #pragma unroll
            for (int mt = 0; mt < 2; mt++)
                #pragma unroll
                for (int p = 0; p < 2; p++) { pa[mt][p][0] = 0.f; pa[mt][p][1] = 0.f; }
            #pragma unroll
            for (int mt = 0; mt < 2; mt++)
                #pragma unroll
                for (int nt = 0; nt < 4; nt++) {
                    #pragma unroll
                    for (int h = 0; h < 2; h++) {
                        pa[mt][0][h] += acc[mt][nt][0] * wtp[h][nt].x
                                      + acc[mt][nt][1] * wtp[h][nt].y;
                        pa[mt][1][h] += acc[mt][nt][2] * wtp[h][nt].x
                                      + acc[mt][nt][3] * wtp[h][nt].y;
                    }
                }
            #pragma unroll
            for (int mt = 0; mt < 2; mt++)
                #pragma unroll
                for (int p = 0; p < 2; p++)
                    #pragma unroll
                    for (int h = 0; h < 2; h++) {
                        float v = pa[mt][p][h];
                        v += __shfl_xor_sync(0xffffffffu, v, 1);
                        v += __shfl_xor_sync(0xffffffffu, v, 2);
                        pa[mt][p][h] = v;
                    }
            if (t == 0) {
                #pragma unroll
                for (int mt = 0; mt < 2; mt++)
                    #pragma unroll
                    for (int p = 0; p < 2; p++) {
                        int r = wm * 32 + mt * 16 + g + 8 * p;
                        *(float2*)&sAp[r * 12 + wn * 2] =
                            make_float2(pa[mt][p][0], pa[mt][p][1]);
                    }
            }
        }
        __syncthreads();                      // bar_b: sAp visible

        // ---- finish alpha, form m partials in regs, reduce over g, atomics ----
        {
            const int b = tile >> 5;
            float al[2][2][2];   // [mt][p][h]
            #pragma unroll
            for (int mt = 0; mt < 2; mt++)
                #pragma unroll
                for (int p = 0; p < 2; p++) {
                    int r = wm * 32 + mt * 16 + g + 8 * p;
                    float2 f0 = *(const float2*)&sAp[r * 12 + 0];
                    float2 f1 = *(const float2*)&sAp[r * 12 + 2];
                    float2 f2 = *(const float2*)&sAp[r * 12 + 4];
                    float2 f3 = *(const float2*)&sAp[r * 12 + 6];
                    al[mt][p][0] = f0.x + f1.x + f2.x + f3.x + cc0;
                    al[mt][p][1] = f0.y + f1.y + f2.y + f3.y + cc1;
                }
            float pm[2][4][2];   // [h][nt][e]
            #pragma unroll
            for (int h = 0; h < 2; h++)
                #pragma unroll
                for (int nt = 0; nt < 4; nt++) {
                    pm[h][nt][0] = al[0][0][h] * acc[0][nt][0] + al[0][1][h] * acc[0][nt][2]
                                 + al[1][0][h] * acc[1][nt][0] + al[1][1][h] * acc[1][nt][2];
                    pm[h][nt][1] = al[0][0][h] * acc[0][nt][1] + al[0][1][h] * acc[0][nt][3]
                                 + al[1][0][h] * acc[1][nt][1] + al[1][1][h] * acc[1][nt][3];
                }
            #pragma unroll
            for (int h = 0; h < 2; h++)
                #pragma unroll
                for (int nt = 0; nt < 4; nt++)
                    #pragma unroll
                    for (int e = 0; e < 2; e++) {
                        float v = pm[h][nt][e];
                        v += __shfl_xor_sync(0xffffffffu, v, 4);
                        v += __shfl_xor_sync(0xffffffffu, v, 8);
                        v += __shfl_xor_sync(0xffffffffu, v, 16);
                        pm[h][nt][e] = v;
                    }
            if (g == 0) {
                #pragma unroll
                for (int h = 0; h < 2; h++)
                    #pragma unroll
                    for (int nt = 0; nt < 4; nt++)
                        #pragma unroll
                        for (int e = 0; e < 2; e++)
                            atomicAdd(&g_m[b * 256 + h * 128 + wn * 32 + nt * 8 + 2 * t + e],
                                      pm[h][nt][e]);
            }
            // abar: wn==0 warps cover all 128 rows exactly once
            if (wn == 0) {
                float s0 = al[0][0][0] + al[0][1][0] + al[1][0][0] + al[1][1][0];
                float s1 = al[0][0][1] + al[0][1][1] + al[1][0][1] + al[1][1][1];
                s0 += __shfl_xor_sync(0xffffffffu, s0, 4);
                s0 += __shfl_xor_sync(0xffffffffu, s0, 8);
                s0 += __shfl_xor_sync(0xffffffffu, s0, 16);
                s1 += __shfl_xor_sync(0xffffffffu, s1, 4);
                s1 += __shfl_xor_sync(0xffffffffu, s1, 8);
                s1 += __shfl_xor_sync(0xffffffffu, s1, 16);
                if (lane == 0) {
                    atomicAdd(&g_ab[b * 2 + 0], s0);
                    atomicAdd(&g_ab[b * 2 + 1], s1);
                }
            }
        }
        tile = nxt;
        nxt = nxt2;
    }

    // ======== Exit protocol + distributed epilogue ========
    if (tid == 0) {
        __threadfence();
        sPrev = atomicAdd(&g_done, 1);
    }
    __syncthreads();
    int rank = sPrev;
    if (rank < EPI_RANK0) return;

    if (tid == 0) {
        while (atomicAdd(&g_done, 0) != GRID_MAIN) __nanosleep(64);
    }
    __syncthreads();
    __threadfence();

    int bb = rank - EPI_RANK0;   // 0..31, unique per epilogue block
    if (tid < 256) e_m[tid] = g_m[bb * 256 + tid];
    if (tid < 2) e_ab[tid] = g_ab[bb * 2 + tid];
    __syncthreads();
    if (tid < 256) g_m[bb * 256 + tid] = 0.f;   // restore for next replay
    if (tid < 2) g_ab[bb * 2 + tid] = 0.f;

    {   // ov[j] = (abar[h]*bv[j] + m[h][:] . Wv[:,j]) / N  (4-way split over p)
        int j = tid & 127, q = tid >> 7, h = j >> 6;
        float p = 0.f;
        #pragma unroll 4
        for (int pp = q * 32; pp < q * 32 + 32; pp++)
            p += e_m[h * 128 + pp] * __ldg(&Wv[pp * 128 + j]);
        e_p[tid] = p;
    }
    __syncthreads();
    if (tid < 128) {
        int h = tid >> 6;
        e_ov[tid] = (e_p[tid] + e_p[128 + tid] + e_p[256 + tid] + e_p[384 + tid]
                     + e_ab[h] * bv[tid]) * (1.0f / N_);
    }
    __syncthreads();
    {   // out[j] = bo[j] + ov . Wo[:,j]
        int j = tid & 127, q = tid >> 7;
        float p = 0.f;
        #pragma unroll 4
        for (int pp = q * 32; pp < q * 32 + 32; pp++)
            p += e_ov[pp] * __ldg(&Wo[pp * 128 + j]);
        e_p[tid] = p;
    }
    __syncthreads();
    if (tid < 128)
        out[bb * 128 + tid] = e_p[tid] + e_p[128 + tid] + e_p[256 + tid]
                              + e_p[384 + tid] + bo[tid];

    if (tid == 0) {
        __threadfence();
        atomicAdd(&g_done2, 1);
        if (rank == GRID_MAIN - 1) {
            while (atomicAdd(&g_done2, 0) != EPI_BLOCKS) __nanosleep(64);
            g_tile = 0; g_done = 0; g_done2 = 0;
        }
    }
}

// ---------------------------------------------------------------------------
extern "C" void kernel_launch(void* const* d_in, const int* in_sizes, int n_in,
                              void* d_out, int out_size) {
    const float* u     = (const float*)d_in[0];
    // d_in[1] = x : unused by the reference
    const float* W1    = (const float*)d_in[2];
    const float* b1    = (const float*)d_in[3];
    const float* W2    = (const float*)d_in[4];
    const float* b2    = (const float*)d_in[5];
    const float* embed = (const float*)d_in[6];
    const float* Wq    = (const float*)d_in[7];
    const float* bq    = (const float*)d_in[8];
    const float* Wk    = (const float*)d_in[9];
    const float* bk    = (const float*)d_in[10];
    const float* Wv    = (const float*)d_in[11];
    const float* bv    = (const float*)d_in[12];
    const float* Wo    = (const float*)d_in[13];
    const float* bo    = (const float*)d_in[14];
    float* out = (float*)d_out;

    const size_t smem_bytes = (size_t)SMEM_FLOATS * sizeof(float);  // 207,904 B
    cudaFuncSetAttribute(main_kernel, cudaFuncAttributeMaxDynamicSharedMemorySize,
                         (int)smem_bytes);

    main_kernel<<<GRID_MAIN, 512, smem_bytes>>>(
        u, W1, b1, W2, b2, embed, Wq, bq, Wk, bk, Wv, bv, Wo, bo, out);
}

// round 12
// speedup vs baseline: 3.1007x; 1.0439x over previous
#include <cuda_runtime.h>

#define B_ 32
#define N_ 4096
#define DU_ 64
#define TROWS 64
#define NTOT2 (B_ * 64)           // 2048 tiles of 64 rows
#define GRID_MAIN 148
#define EPI_BLOCKS 32
#define EPI_RANK0 (GRID_MAIN - EPI_BLOCKS)

// Globals (zero at load; every replay restores them to zero)
__device__ float g_m[B_ * 256];   // moment accumulators [b][h*128+j]
__device__ float g_ab[B_ * 2];    // alpha-sum accumulators
__device__ int   g_tile;
__device__ int   g_done;
__device__ int   g_done2;

__device__ __forceinline__ float tanh_fast(float x) {
    float y; asm("tanh.approx.f32 %0, %1;" : "=f"(y) : "f"(x)); return y;
}
__device__ __forceinline__ float gelu_tanh(float x) {
    const float k0 = 0.7978845608028654f;
    float inner = k0 * (x + 0.044715f * x * x * x);
    return 0.5f * x * (1.0f + tanh_fast(inner));
}
__device__ __forceinline__ unsigned f2tf32(float x) {
    unsigned y; asm("cvt.rna.tf32.f32 %0, %1;" : "=r"(y) : "f"(x)); return y;
}
__device__ __forceinline__ float tf32f(float x) { return __uint_as_float(f2tf32(x)); }

__device__ __forceinline__ void mma8(float* c, const unsigned* a, unsigned b0, unsigned b1) {
    asm volatile(
        "mma.sync.aligned.m16n8k8.row.col.f32.tf32.tf32.f32 "
        "{%0,%1,%2,%3}, {%4,%5,%6,%7}, {%8,%9}, {%0,%1,%2,%3};\n"
        : "+f"(c[0]), "+f"(c[1]), "+f"(c[2]), "+f"(c[3])
        : "r"(a[0]), "r"(a[1]), "r"(a[2]), "r"(a[3]), "r"(b0), "r"(b1));
}

// ---------------------------------------------------------------------------
// SMEM layout (floats). B operands in FRAGMENT ORDER, stride 8 + XOR swizzle
// (conflict-free LDS.64; see R6). A operands: strides 68/132 (= 4 mod 32),
// lane addr 4g+t distinct: conflict-free. Per-group sAp stride 12.
// ---------------------------------------------------------------------------
#define OFF_B1   0        // 4 x 8  x 256 = 8192
#define OFF_B2   8192     // 4 x 16 x 256 = 16384 -> 24576
#define OFF_U0   24576    // 64 x 68 = 4352 -> 28928
#define OFF_U1   28928    // -> 33280
#define OFF_Z0   33280    // 64 x 132 = 8448 -> 41728
#define OFF_Z1G  41728    // -> 50176
#define OFF_WT   50176    // 256 wt + 2 c (+pad 6) -> 50440
#define OFF_AP0  50440    // 64 x 12 = 768 -> 51208
#define OFF_AP1  51208    // -> 51976
#define SMEM_FLOATS 51976 // 207,904 bytes
// sQ (prologue scratch, 384 floats) aliases OFF_Z0.

template<int SA, int KSTEPS>
__device__ __forceinline__ void gemm_fr(const float* __restrict__ A,
                                        const float* __restrict__ Bw,
                                        float acc[2][4][4],
                                        int wm, int g, int t, int lane, int xv) {
    unsigned a[2][2][4];
    float2 bp[2][4];
    {   // preload kstep 0
        #pragma unroll
        for (int mt = 0; mt < 2; mt++) {
            int r = wm * 32 + mt * 16 + g;
            a[0][mt][0] = __float_as_uint(A[r * SA + t]);
            a[0][mt][1] = __float_as_uint(A[(r + 8) * SA + t]);
            a[0][mt][2] = __float_as_uint(A[r * SA + t + 4]);
            a[0][mt][3] = __float_as_uint(A[(r + 8) * SA + t + 4]);
        }
        const float* bl = Bw + lane * 8;
        #pragma unroll
        for (int nt = 0; nt < 4; nt++) bp[0][nt] = *(const float2*)&bl[(nt ^ xv) * 2];
    }
    #pragma unroll
    for (int s = 0; s < KSTEPS; s++) {
        int cur = s & 1, nxt = cur ^ 1;
        if (s + 1 < KSTEPS) {
            int kk = (s + 1) * 8 + t;
            #pragma unroll
            for (int mt = 0; mt < 2; mt++) {
                int r = wm * 32 + mt * 16 + g;
                a[nxt][mt][0] = __float_as_uint(A[r * SA + kk]);
                a[nxt][mt][1] = __float_as_uint(A[(r + 8) * SA + kk]);
                a[nxt][mt][2] = __float_as_uint(A[r * SA + kk + 4]);
                a[nxt][mt][3] = __float_as_uint(A[(r + 8) * SA + kk + 4]);
            }
            const float* bl = Bw + (s + 1) * 256 + lane * 8;
            #pragma unroll
            for (int nt = 0; nt < 4; nt++) bp[nxt][nt] = *(const float2*)&bl[(nt ^ xv) * 2];
        }
        #pragma unroll
        for (int nt = 0; nt < 4; nt++) {
            unsigned b0 = __float_as_uint(bp[cur][nt].x);
            unsigned b1 = __float_as_uint(bp[cur][nt].y);
            mma8(acc[0][nt], a[cur][0], b0, b1);
            mma8(acc[1][nt], a[cur][1], b0, b1);
        }
    }
}

// ---------------------------------------------------------------------------
// Single persistent kernel. grid = 148 x 512 threads = 2 independent groups
// of 8 warps (2m x 4n over a 64x128 tile), group-scoped named barriers.
// ---------------------------------------------------------------------------
__global__ __launch_bounds__(512, 1)
void main_kernel(const float* __restrict__ u,
                 const float* __restrict__ W1, const float* __restrict__ b1,
                 const float* __restrict__ W2, const float* __restrict__ b2,
                 const float* __restrict__ embed,
                 const float* __restrict__ Wq, const float* __restrict__ bq,
                 const float* __restrict__ Wk, const float* __restrict__ bk,
                 const float* __restrict__ Wv, const float* __restrict__ bv,
                 const float* __restrict__ Wo, const float* __restrict__ bo,
                 float* __restrict__ out) {
    extern __shared__ float sm[];
    float* sB1 = sm + OFF_B1;
    float* sB2 = sm + OFF_B2;
    float* sWT = sm + OFF_WT;
    float* sQ  = sm + OFF_Z0;   // prologue scratch

    __shared__ int sTile[2];
    __shared__ int sPrev;
    __shared__ float e_m[256], e_ab[2], e_ov[128], e_p[512];

    const int tid = threadIdx.x;
    const int lane = tid & 31, warp = tid >> 5;
    const int grp = warp >> 3;                 // 0 or 1
    const int lt = tid & 255;                  // id within group
    const int w8 = warp & 7;
    const int wm = w8 & 1, wn = w8 >> 1;       // 2m x 4n, warp tile 32x32
    const int g = lane >> 2, t = lane & 3;
    const int xv = g & 3;
    const int barid = grp + 1;

    float* sU  = sm + (grp ? OFF_U1 : OFF_U0);
    float* sZ1 = sm + (grp ? OFF_Z1G : OFF_Z0);
    float* sAp = sm + (grp ? OFF_AP1 : OFF_AP0);

#define GBAR() asm volatile("bar.sync %0, 256;" :: "r"(barid) : "memory")

    // ======== Prologue A: pack W1/W2 into fragment order (tf32, swizzled) ====
    #pragma unroll 2
    for (int idx = tid; idx < 4096; idx += 512) {   // W1: 4w x 8s x 32l x 4nt
        int nt = idx & 3, ln = (idx >> 2) & 31, s = (idx >> 7) & 7, w = idx >> 10;
        int tt = ln & 3, gg = ln >> 2;
        int n = w * 32 + nt * 8 + gg;
        int k = s * 8 + tt;
        float* d = &sB1[(w * 8 + s) * 256 + ln * 8 + ((nt ^ (gg & 3)) * 2)];
        d[0] = tf32f(W1[k * 128 + n]);
        d[1] = tf32f(W1[(k + 4) * 128 + n]);
    }
    #pragma unroll 2
    for (int idx = tid; idx < 8192; idx += 512) {   // W2: 4w x 16s x 32l x 4nt
        int nt = idx & 3, ln = (idx >> 2) & 31, s = (idx >> 7) & 15, w = idx >> 11;
        int tt = ln & 3, gg = ln >> 2;
        int n = w * 32 + nt * 8 + gg;
        int k = s * 8 + tt;
        float* d = &sB2[(w * 16 + s) * 256 + ln * 8 + ((nt ^ (gg & 3)) * 2)];
        d[0] = tf32f(W2[k * 128 + n]);
        d[1] = tf32f(W2[(k + 4) * 128 + n]);
    }

    // ======== Prologue B: q, w~, c ========
    if (tid < 256) {
        int j = tid & 127, half = tid >> 7;
        float p = 0.f;
        #pragma unroll 4
        for (int i = half * 64; i < half * 64 + 64; i++) p += embed[i] * Wq[i * 128 + j];
        sQ[half * 128 + j] = p;
    }
    __syncthreads();
    if (tid < 128) sQ[256 + tid] = bq[tid] + sQ[tid] + sQ[128 + tid];
    __syncthreads();
    if (tid < 256) {
        int h = tid >> 7, i = tid & 127;
        const float* qh = &sQ[256 + h * 64];
        const float* wk = &Wk[i * 128 + h * 64];
        float s0 = 0.f, s1 = 0.f, s2 = 0.f, s3 = 0.f;
        #pragma unroll 8
        for (int d = 0; d < 64; d += 4) {
            s0 += wk[d] * qh[d];         s1 += wk[d + 1] * qh[d + 1];
            s2 += wk[d + 2] * qh[d + 2]; s3 += wk[d + 3] * qh[d + 3];
        }
        sWT[tid] = (s0 + s1) + (s2 + s3);
    }
    if (tid < 2) {
        const float* qh = &sQ[256 + tid * 64];
        float s = 0.f;
        #pragma unroll 8
        for (int d = 0; d < 64; d++) s += bk[tid * 64 + d] * qh[d];
        sWT[256 + tid] = s;
    }
    __syncthreads();

    // persistent per-thread constants
    float2 wtp[2][4];
    #pragma unroll
    for (int h = 0; h < 2; h++)
        #pragma unroll
        for (int nt = 0; nt < 4; nt++)
            wtp[h][nt] = *(const float2*)&sWT[h * 128 + wn * 32 + nt * 8 + 2 * t];
    const float cc0 = sWT[256], cc1 = sWT[257];

    if (lt == 0) sTile[grp] = atomicAdd(&g_tile, 1);
    __syncthreads();   // sQ dead (it aliased group-0 Z1); tickets visible
    int tile = sTile[grp];

    // prefetch first u tile (64 rows x 64 cols = 1024 float4; 4/thread)
    float4 up[4];
    if (tile < NTOT2) {
        int bb = tile >> 6, r0 = (tile & 63) * TROWS;
        const float4* src = (const float4*)(u + ((size_t)bb * N_ + r0) * DU_);
        #pragma unroll
        for (int it = 0; it < 4; it++) up[it] = src[lt + it * 256];
    }

    // ======== Persistent per-group tile loop (3 named barriers) ========
    while (tile < NTOT2) {
        const int b = tile >> 6;

        // stage u (RN tf32)
        #pragma unroll
        for (int it = 0; it < 4; it++) {
            int i = lt + it * 256;
            int r = i >> 4, c4 = i & 15;
            float* d = &sU[r * 68 + c4 * 4];
            d[0] = tf32f(up[it].x); d[1] = tf32f(up[it].y);
            d[2] = tf32f(up[it].z); d[3] = tf32f(up[it].w);
        }
        if (lt == 0) sTile[grp] = atomicAdd(&g_tile, 1);
        GBAR();                               // bar1: sU + ticket
        int nxt = sTile[grp];

        // ---- Stage 1: Z1 = gelu(U @ W1 + b1), K=64 ----
        float acc[2][4][4];
        #pragma unroll
        for (int mt = 0; mt < 2; mt++)
            #pragma unroll
            for (int nt = 0; nt < 4; nt++)
                #pragma unroll
                for (int e = 0; e < 4; e++) acc[mt][nt][e] = 0.f;

        gemm_fr<68, 8>(sU, sB1 + wn * (8 * 256), acc, wm, g, t, lane, xv);

        #pragma unroll
        for (int nt = 0; nt < 4; nt++) {
            int c0 = wn * 32 + nt * 8 + 2 * t;
            float bc0 = __ldg(&b1[c0]), bc1 = __ldg(&b1[c0 + 1]);
            #pragma unroll
            for (int mt = 0; mt < 2; mt++) {
                int r = wm * 32 + mt * 16 + g;
                sZ1[r * 132 + c0]           = tf32f(gelu_tanh(acc[mt][nt][0] + bc0));
                sZ1[r * 132 + c0 + 1]       = tf32f(gelu_tanh(acc[mt][nt][1] + bc1));
                sZ1[(r + 8) * 132 + c0]     = tf32f(gelu_tanh(acc[mt][nt][2] + bc0));
                sZ1[(r + 8) * 132 + c0 + 1] = tf32f(gelu_tanh(acc[mt][nt][3] + bc1));
            }
        }
        GBAR();                               // bar2: sZ1 visible

        // prefetch u(nxt); LDG latency hides behind gemm2
        if (nxt < NTOT2) {
            int bb = nxt >> 6, r0 = (nxt & 63) * TROWS;
            const float4* src = (const float4*)(u + ((size_t)bb * N_ + r0) * DU_);
            #pragma unroll
            for (int it = 0; it < 4; it++) up[it] = src[lt + it * 256];
        }

        // ---- Stage 2: Z2 = gelu(Z1 @ W2 + b2), K=128 (stays in registers) ----
        #pragma unroll
        for (int mt = 0; mt < 2; mt++)
            #pragma unroll
            for (int nt = 0; nt < 4; nt++)
                #pragma unroll
                for (int e = 0; e < 4; e++) acc[mt][nt][e] = 0.f;

        gemm_fr<132, 16>(sZ1, sB2 + wn * (16 * 256), acc, wm, g, t, lane, xv);

        #pragma unroll
        for (int nt = 0; nt < 4; nt++) {
            int c0 = wn * 32 + nt * 8 + 2 * t;
            float bc0 = __ldg(&b2[c0]), bc1 = __ldg(&b2[c0 + 1]);
            acc[0][nt][0] = gelu_tanh(acc[0][nt][0] + bc0);
            acc[0][nt][1] = gelu_tanh(acc[0][nt][1] + bc1);
            acc[0][nt][2] = gelu_tanh(acc[0][nt][2] + bc0);
            acc[0][nt][3] = gelu_tanh(acc[0][nt][3] + bc1);
            acc[1][nt][0] = gelu_tanh(acc[1][nt][0] + bc0);
            acc[1][nt][1] = gelu_tanh(acc[1][nt][1] + bc1);
            acc[1][nt][2] = gelu_tanh(acc[1][nt][2] + bc0);
            acc[1][nt][3] = gelu_tanh(acc[1][nt][3] + bc1);
        }

        // ---- alpha partials over this warp's 32 cols; reduce over t-lanes ----
        {
            float pa[2][2][2];   // [mt][p][h]
            #pragma unroll
            for (int mt = 0; mt < 2; mt++)
                #pragma unroll
                for (int p = 0; p < 2; p++) { pa[mt][p][0] = 0.f; pa[mt][p][1] = 0.f; }
            #pragma unroll
            for (int mt = 0; mt < 2; mt++)
                #pragma unroll
                for (int nt = 0; nt < 4; nt++) {
                    #pragma unroll
                    for (int h = 0; h < 2; h++) {
                        pa[mt][0][h] += acc[mt][nt][0] * wtp[h][nt].x
                                      + acc[mt][nt][1] * wtp[h][nt].y;
                        pa[mt][1][h] += acc[mt][nt][2] * wtp[h][nt].x
                                      + acc[mt][nt][3] * wtp[h][nt].y;
                    }
                }
            #pragma unroll
            for (int mt = 0; mt < 2; mt++)
                #pragma unroll
                for (int p = 0; p < 2; p++)
                    #pragma unroll
                    for (int h = 0; h < 2; h++) {
                        float v = pa[mt][p][h];
                        v += __shfl_xor_sync(0xffffffffu, v, 1);
                        v += __shfl_xor_sync(0xffffffffu, v, 2);
                        pa[mt][p][h] = v;
                    }
            if (t == 0) {
                #pragma unroll
                for (int mt = 0; mt < 2; mt++)
                    #pragma unroll
                    for (int p = 0; p < 2; p++) {
                        int r = wm * 32 + mt * 16 + g + 8 * p;
                        *(float2*)&sAp[r * 12 + wn * 2] =
                            make_float2(pa[mt][p][0], pa[mt][p][1]);
                    }
            }
        }
        GBAR();                               // bar3: sAp visible

        // ---- finish alpha, form m partials, reduce over g, atomics ----
        {
            float al[2][2][2];   // [mt][p][h]
            #pragma unroll
            for (int mt = 0; mt < 2; mt++)
                #pragma unroll
                for (int p = 0; p < 2; p++) {
                    int r = wm * 32 + mt * 16 + g + 8 * p;
                    float2 f0 = *(const float2*)&sAp[r * 12 + 0];
                    float2 f1 = *(const float2*)&sAp[r * 12 + 2];
                    float2 f2 = *(const float2*)&sAp[r * 12 + 4];
                    float2 f3 = *(const float2*)&sAp[r * 12 + 6];
                    al[mt][p][0] = f0.x + f1.x + f2.x + f3.x + cc0;
                    al[mt][p][1] = f0.y + f1.y + f2.y + f3.y + cc1;
                }
            float pm[2][4][2];   // [h][nt][e]
            #pragma unroll
            for (int h = 0; h < 2; h++)
                #pragma unroll
                for (int nt = 0; nt < 4; nt++) {
                    pm[h][nt][0] = al[0][0][h] * acc[0][nt][0] + al[0][1][h] * acc[0][nt][2]
                                 + al[1][0][h] * acc[1][nt][0] + al[1][1][h] * acc[1][nt][2];
                    pm[h][nt][1] = al[0][0][h] * acc[0][nt][1] + al[0][1][h] * acc[0][nt][3]
                                 + al[1][0][h] * acc[1][nt][1] + al[1][1][h] * acc[1][nt][3];
                }
            #pragma unroll
            for (int h = 0; h < 2; h++)
                #pragma unroll
                for (int nt = 0; nt < 4; nt++)
                    #pragma unroll
                    for (int e = 0; e < 2; e++) {
                        float v = pm[h][nt][e];
                        v += __shfl_xor_sync(0xffffffffu, v, 4);
                        v += __shfl_xor_sync(0xffffffffu, v, 8);
                        v += __shfl_xor_sync(0xffffffffu, v, 16);
                        pm[h][nt][e] = v;
                    }
            if (g == 0) {
                #pragma unroll
                for (int h = 0; h < 2; h++)
                    #pragma unroll
                    for (int nt = 0; nt < 4; nt++)
                        #pragma unroll
                        for (int e = 0; e < 2; e++)
                            atomicAdd(&g_m[b * 256 + h * 128 + wn * 32 + nt * 8 + 2 * t + e],
                                      pm[h][nt][e]);
            }
            // abar: wn==0 warps (wm 0,1) cover all 64 rows exactly once
            if (wn == 0) {
                float s0 = al[0][0][0] + al[0][1][0] + al[1][0][0] + al[1][1][0];
                float s1 = al[0][0][1] + al[0][1][1] + al[1][0][1] + al[1][1][1];
                s0 += __shfl_xor_sync(0xffffffffu, s0, 4);
                s0 += __shfl_xor_sync(0xffffffffu, s0, 8);
                s0 += __shfl_xor_sync(0xffffffffu, s0, 16);
                s1 += __shfl_xor_sync(0xffffffffu, s1, 4);
                s1 += __shfl_xor_sync(0xffffffffu, s1, 8);
                s1 += __shfl_xor_sync(0xffffffffu, s1, 16);
                if (lane == 0) {
                    atomicAdd(&g_ab[b * 2 + 0], s0);
                    atomicAdd(&g_ab[b * 2 + 1], s1);
                }
            }
        }
        tile = nxt;
    }

    // ======== Exit protocol + distributed epilogue ========
    __syncthreads();   // join both groups
    if (tid == 0) { __threadfence(); sPrev = atomicAdd(&g_done, 1); }
    __syncthreads();
    int rank = sPrev;
    if (rank < EPI_RANK0) return;
    if (tid == 0) { while (atomicAdd(&g_done, 0) != GRID_MAIN) __nanosleep(64); }
    __syncthreads();
    __threadfence();

    int bb = rank - EPI_RANK0;   // 0..31, unique per epilogue block
    if (tid < 256) e_m[tid] = g_m[bb * 256 + tid];
    if (tid < 2) e_ab[tid] = g_ab[bb * 2 + tid];
    __syncthreads();
    if (tid < 256) g_m[bb * 256 + tid] = 0.f;   // restore for next replay
    if (tid < 2) g_ab[bb * 2 + tid] = 0.f;

    {   // ov[j] = (abar[h]*bv[j] + m[h][:] . Wv[:,j]) / N
        int j = tid & 127, q = tid >> 7, h = j >> 6;
        float p = 0.f;
        #pragma unroll 4
        for (int pp = q * 32; pp < q * 32 + 32; pp++)
            p += e_m[h * 128 + pp] * __ldg(&Wv[pp * 128 + j]);
        e_p[tid] = p;
    }
    __syncthreads();
    if (tid < 128) {
        int h = tid >> 6;
        e_ov[tid] = (e_p[tid] + e_p[128 + tid] + e_p[256 + tid] + e_p[384 + tid]
                     + e_ab[h] * bv[tid]) * (1.0f / N_);
    }
    __syncthreads();
    {   // out[j] = bo[j] + ov . Wo[:,j]
        int j = tid & 127, q = tid >> 7;
        float p = 0.f;
        #pragma unroll 4
        for (int pp = q * 32; pp < q * 32 + 32; pp++)
            p += e_ov[pp] * __ldg(&Wo[pp * 128 + j]);
        e_p[tid] = p;
    }
    __syncthreads();
    if (tid < 128)
        out[bb * 128 + tid] = e_p[tid] + e_p[128 + tid] + e_p[256 + tid]
                              + e_p[384 + tid] + bo[tid];

    if (tid == 0) {
        __threadfence();
        atomicAdd(&g_done2, 1);
        if (rank == GRID_MAIN - 1) {
            while (atomicAdd(&g_done2, 0) != EPI_BLOCKS) __nanosleep(64);
            g_tile = 0; g_done = 0; g_done2 = 0;
        }
    }
#undef GBAR
}

// ---------------------------------------------------------------------------
extern "C" void kernel_launch(void* const* d_in, const int* in_sizes, int n_in,
                              void* d_out, int out_size) {
    const float* u     = (const float*)d_in[0];
    // d_in[1] = x : unused by the reference
    const float* W1    = (const float*)d_in[2];
    const float* b1    = (const float*)d_in[3];
    const float* W2    = (const float*)d_in[4];
    const float* b2    = (const float*)d_in[5];
    const float* embed = (const float*)d_in[6];
    const float* Wq    = (const float*)d_in[7];
    const float* bq    = (const float*)d_in[8];
    const float* Wk    = (const float*)d_in[9];
    const float* bk    = (const float*)d_in[10];
    const float* Wv    = (const float*)d_in[11];
    const float* bv    = (const float*)d_in[12];
    const float* Wo    = (const float*)d_in[13];
    const float* bo    = (const float*)d_in[14];
    float* out = (float*)d_out;

    const size_t smem_bytes = (size_t)SMEM_FLOATS * sizeof(float);  // 207,904 B
    cudaFuncSetAttribute(main_kernel, cudaFuncAttributeMaxDynamicSharedMemorySize,
                         (int)smem_bytes);

    main_kernel<<<GRID_MAIN, 512, smem_bytes>>>(
        u, W1, b1, W2, b2, embed, Wq, bq, Wk, bk, Wv, bv, Wo, bo, out);
}

// round 15
// speedup vs baseline: 3.8380x; 1.2378x over previous
#include <cuda_runtime.h>
#include <cuda_fp16.h>

#define B_ 32
#define N_ 4096
#define DU_ 64
#define TROWS 64
#define NTOT2 (B_ * 64)           // 2048 tiles of 64 rows
#define GRID_MAIN 148
#define EPI_BLOCKS 32
#define EPI_RANK0 (GRID_MAIN - EPI_BLOCKS)

// Globals (zero at load; every replay restores them to zero)
__device__ float g_m[B_ * 256];   // moment accumulators [b][h*128+j]
__device__ float g_ab[B_ * 2];    // alpha-sum accumulators
__device__ int   g_tile;
__device__ int   g_done;
__device__ int   g_done2;

__device__ __forceinline__ float tanh_fast(float x) {
    float y; asm("tanh.approx.f32 %0, %1;" : "=f"(y) : "f"(x)); return y;
}
__device__ __forceinline__ float gelu_tanh(float x) {
    const float k0 = 0.7978845608028654f;
    float inner = k0 * (x + 0.044715f * x * x * x);
    return 0.5f * x * (1.0f + tanh_fast(inner));
}
__device__ __forceinline__ unsigned pk16(float a, float b) {
    __half2 h = __floats2half2_rn(a, b);
    return *(unsigned*)&h;
}

// fp16 mma: D(16x8,f32) += A(16x16,f16) x B(16x8,f16)
__device__ __forceinline__ void mma16(float* c, const unsigned* a, unsigned b0, unsigned b1) {
    asm volatile(
        "mma.sync.aligned.m16n8k16.row.col.f32.f16.f16.f32 "
        "{%0,%1,%2,%3}, {%4,%5,%6,%7}, {%8,%9}, {%0,%1,%2,%3};\n"
        : "+f"(c[0]), "+f"(c[1]), "+f"(c[2]), "+f"(c[3])
        : "r"(a[0]), "r"(a[1]), "r"(a[2]), "r"(a[3]), "r"(b0), "r"(b1));
}

// ---------------------------------------------------------------------------
// SMEM layout (32-bit word units). fp16 operands packed 2-per-word along K.
// A regions: word strides 36/68 (= 4 mod 32), lane addr 4g+t distinct:
// conflict-free. B in FRAGMENT ORDER, stride 8 + XOR swizzle (conflict-free
// LDS.64; proof as R6). Per-group sAp stride 12.
// ---------------------------------------------------------------------------
#define OFF_B1   0        // 4w x 4s x 256 = 4096
#define OFF_B2   4096     // 4w x 8s x 256 = 8192 -> 12288
#define OFF_U0   12288    // 64 x 36 = 2304 -> 14592
#define OFF_U1   14592    // -> 16896
#define OFF_Z0   16896    // 64 x 68 = 4352 -> 21248
#define OFF_Z1G  21248    // -> 25600
#define OFF_WT   25600    // 256 wt + 2 c (+pad 6) -> 25864
#define OFF_AP0  25864    // 64 x 12 = 768 -> 26632
#define OFF_AP1  26632    // -> 27400
#define SMEM_FLOATS 27400 // 109,600 bytes
// sQ (prologue scratch, 384 floats) aliases OFF_Z0.

template<int SA, int KSTEPS>
__device__ __forceinline__ void gemm16(const unsigned* __restrict__ A,
                                       const unsigned* __restrict__ Bw,
                                       float acc[2][4][4],
                                       int wm, int g, int t, int lane, int xv) {
    unsigned a[2][2][4];
    uint2 bp[2][4];
    {   // preload kstep 0
        #pragma unroll
        for (int mt = 0; mt < 2; mt++) {
            int r = wm * 32 + mt * 16 + g;
            a[0][mt][0] = A[r * SA + t];
            a[0][mt][1] = A[(r + 8) * SA + t];
            a[0][mt][2] = A[r * SA + t + 4];
            a[0][mt][3] = A[(r + 8) * SA + t + 4];
        }
        const unsigned* bl = Bw + lane * 8;
        #pragma unroll
        for (int nt = 0; nt < 4; nt++) bp[0][nt] = *(const uint2*)&bl[(nt ^ xv) * 2];
    }
    #pragma unroll
    for (int s = 0; s < KSTEPS; s++) {
        int cur = s & 1, nx = cur ^ 1;
        if (s + 1 < KSTEPS) {
            int kw = (s + 1) * 8 + t;
            #pragma unroll
            for (int mt = 0; mt < 2; mt++) {
                int r = wm * 32 + mt * 16 + g;
                a[nx][mt][0] = A[r * SA + kw];
                a[nx][mt][1] = A[(r + 8) * SA + kw];
                a[nx][mt][2] = A[r * SA + kw + 4];
                a[nx][mt][3] = A[(r + 8) * SA + kw + 4];
            }
            const unsigned* bl = Bw + (s + 1) * 256 + lane * 8;
            #pragma unroll
            for (int nt = 0; nt < 4; nt++) bp[nx][nt] = *(const uint2*)&bl[(nt ^ xv) * 2];
        }
        #pragma unroll
        for (int nt = 0; nt < 4; nt++) {
            mma16(acc[0][nt], a[cur][0], bp[cur][nt].x, bp[cur][nt].y);
            mma16(acc[1][nt], a[cur][1], bp[cur][nt].x, bp[cur][nt].y);
        }
    }
}

// ---------------------------------------------------------------------------
// Single persistent kernel. grid = 148 x 512 threads = 2 independent groups
// of 8 warps (2m x 4n over a 64x128 tile), group-scoped named barriers.
// ---------------------------------------------------------------------------
__global__ __launch_bounds__(512, 1)
void main_kernel(const float* __restrict__ u,
                 const float* __restrict__ W1, const float* __restrict__ b1,
                 const float* __restrict__ W2, const float* __restrict__ b2,
                 const float* __restrict__ embed,
                 const float* __restrict__ Wq, const float* __restrict__ bq,
                 const float* __restrict__ Wk, const float* __restrict__ bk,
                 const float* __restrict__ Wv, const float* __restrict__ bv,
                 const float* __restrict__ Wo, const float* __restrict__ bo,
                 float* __restrict__ out) {
    extern __shared__ float sm[];
    unsigned* sB1u = (unsigned*)(sm + OFF_B1);
    unsigned* sB2u = (unsigned*)(sm + OFF_B2);
    float* sWT = sm + OFF_WT;
    float* sQ  = sm + OFF_Z0;   // prologue scratch

    __shared__ int sTile[2];
    __shared__ int sPrev;
    __shared__ float e_m[256], e_ab[2], e_ov[128], e_p[512];

    const int tid = threadIdx.x;
    const int lane = tid & 31, warp = tid >> 5;
    const int grp = warp >> 3;                 // 0 or 1
    const int lt = tid & 255;                  // id within group
    const int w8 = warp & 7;
    const int wm = w8 & 1, wn = w8 >> 1;       // 2m x 4n, warp tile 32x32
    const int g = lane >> 2, t = lane & 3;
    const int xv = g & 3;
    const int barid = grp + 1;

    unsigned* sU16 = (unsigned*)(sm + (grp ? OFF_U1 : OFF_U0));
    unsigned* sZ1u = (unsigned*)(sm + (grp ? OFF_Z1G : OFF_Z0));
    float* sAp = sm + (grp ? OFF_AP1 : OFF_AP0);

#define GBAR() asm volatile("bar.sync %0, 256;" :: "r"(barid) : "memory")

    // ======== Prologue A: pack W1/W2 into fp16 fragment order ========
    #pragma unroll 2
    for (int idx = tid; idx < 2048; idx += 512) {   // W1: 4w x 4s x 32l x 4nt
        int nt = idx & 3, ln = (idx >> 2) & 31, s = (idx >> 7) & 3, w = idx >> 9;
        int tt = ln & 3, gg = ln >> 2;
        int n = w * 32 + nt * 8 + gg;
        int k0 = s * 16 + 2 * tt;
        unsigned* d = &sB1u[(w * 4 + s) * 256 + ln * 8 + ((nt ^ (gg & 3)) * 2)];
        d[0] = pk16(W1[k0 * 128 + n],       W1[(k0 + 1) * 128 + n]);
        d[1] = pk16(W1[(k0 + 8) * 128 + n], W1[(k0 + 9) * 128 + n]);
    }
    #pragma unroll 2
    for (int idx = tid; idx < 4096; idx += 512) {   // W2: 4w x 8s x 32l x 4nt
        int nt = idx & 3, ln = (idx >> 2) & 31, s = (idx >> 7) & 7, w = idx >> 10;
        int tt = ln & 3, gg = ln >> 2;
        int n = w * 32 + nt * 8 + gg;
        int k0 = s * 16 + 2 * tt;
        unsigned* d = &sB2u[(w * 8 + s) * 256 + ln * 8 + ((nt ^ (gg & 3)) * 2)];
        d[0] = pk16(W2[k0 * 128 + n],       W2[(k0 + 1) * 128 + n]);
        d[1] = pk16(W2[(k0 + 8) * 128 + n], W2[(k0 + 9) * 128 + n]);
    }

    // ======== Prologue B: q, w~, c ========
    if (tid < 256) {
        int j = tid & 127, half = tid >> 7;
        float p = 0.f;
        #pragma unroll 4
        for (int i = half * 64; i < half * 64 + 64; i++) p += embed[i] * Wq[i * 128 + j];
        sQ[half * 128 + j] = p;
    }
    __syncthreads();
    if (tid < 128) sQ[256 + tid] = bq[tid] + sQ[tid] + sQ[128 + tid];
    __syncthreads();
    if (tid < 256) {
        int h = tid >> 7, i = tid & 127;
        const float* qh = &sQ[256 + h * 64];
        const float* wk = &Wk[i * 128 + h * 64];
        float s0 = 0.f, s1 = 0.f, s2 = 0.f, s3 = 0.f;
        #pragma unroll 8
        for (int d = 0; d < 64; d += 4) {
            s0 += wk[d] * qh[d];         s1 += wk[d + 1] * qh[d + 1];
            s2 += wk[d + 2] * qh[d + 2]; s3 += wk[d + 3] * qh[d + 3];
        }
        sWT[tid] = (s0 + s1) + (s2 + s3);
    }
    if (tid < 2) {
        const float* qh = &sQ[256 + tid * 64];
        float s = 0.f;
        #pragma unroll 8
        for (int d = 0; d < 64; d++) s += bk[tid * 64 + d] * qh[d];
        sWT[256 + tid] = s;
    }
    __syncthreads();

    // persistent per-thread constants
    float2 wtp[2][4];
    #pragma unroll
    for (int h = 0; h < 2; h++)
        #pragma unroll
        for (int nt = 0; nt < 4; nt++)
            wtp[h][nt] = *(const float2*)&sWT[h * 128 + wn * 32 + nt * 8 + 2 * t];
    const float cc0 = sWT[256], cc1 = sWT[257];

    if (lt == 0) sTile[grp] = atomicAdd(&g_tile, 1);
    __syncthreads();   // sQ dead (aliased group-0 Z1); tickets visible
    int tile = sTile[grp];

    // prefetch first u tile (64 rows x 64 cols = 1024 float4; 4/thread)
    float4 up[4];
    if (tile < NTOT2) {
        int bb = tile >> 6, r0 = (tile & 63) * TROWS;
        const float4* src = (const float4*)(u + ((size_t)bb * N_ + r0) * DU_);
        #pragma unroll
        for (int it = 0; it < 4; it++) up[it] = src[lt + it * 256];
    }

    // ======== Persistent per-group tile loop (3 named barriers) ========
    while (tile < NTOT2) {
        const int b = tile >> 6;

        // stage u as fp16 (RN), STS.64 conflict-free
        #pragma unroll
        for (int it = 0; it < 4; it++) {
            int i = lt + it * 256;
            int r = i >> 4, c2 = (i & 15) * 2;
            uint2 v;
            v.x = pk16(up[it].x, up[it].y);
            v.y = pk16(up[it].z, up[it].w);
            *(uint2*)&sU16[r * 36 + c2] = v;
        }
        if (lt == 0) sTile[grp] = atomicAdd(&g_tile, 1);
        GBAR();                               // bar1: sU + ticket
        int nxt = sTile[grp];

        // ---- Stage 1: Z1 = gelu(U @ W1 + b1), K=64 (4 ksteps) ----
        float acc[2][4][4];
        #pragma unroll
        for (int mt = 0; mt < 2; mt++)
            #pragma unroll
            for (int nt = 0; nt < 4; nt++)
                #pragma unroll
                for (int e = 0; e < 4; e++) acc[mt][nt][e] = 0.f;

        gemm16<36, 4>(sU16, sB1u + wn * (4 * 256), acc, wm, g, t, lane, xv);

        #pragma unroll
        for (int nt = 0; nt < 4; nt++) {
            int c0 = wn * 32 + nt * 8 + 2 * t;
            float bc0 = __ldg(&b1[c0]), bc1 = __ldg(&b1[c0 + 1]);
            int wi = c0 >> 1;   // packed word index
            #pragma unroll
            for (int mt = 0; mt < 2; mt++) {
                int r = wm * 32 + mt * 16 + g;
                sZ1u[r * 68 + wi] =
                    pk16(gelu_tanh(acc[mt][nt][0] + bc0), gelu_tanh(acc[mt][nt][1] + bc1));
                sZ1u[(r + 8) * 68 + wi] =
                    pk16(gelu_tanh(acc[mt][nt][2] + bc0), gelu_tanh(acc[mt][nt][3] + bc1));
            }
        }
        GBAR();                               // bar2: sZ1 visible

        // prefetch u(nxt); LDG latency hides behind gemm2
        if (nxt < NTOT2) {
            int bb = nxt >> 6, r0 = (nxt & 63) * TROWS;
            const float4* src = (const float4*)(u + ((size_t)bb * N_ + r0) * DU_);
            #pragma unroll
            for (int it = 0; it < 4; it++) up[it] = src[lt + it * 256];
        }

        // ---- Stage 2: Z2 = gelu(Z1 @ W2 + b2), K=128 (8 ksteps; regs) ----
        #pragma unroll
        for (int mt = 0; mt < 2; mt++)
            #pragma unroll
            for (int nt = 0; nt < 4; nt++)
                #pragma unroll
                for (int e = 0; e < 4; e++) acc[mt][nt][e] = 0.f;

        gemm16<68, 8>(sZ1u, sB2u + wn * (8 * 256), acc, wm, g, t, lane, xv);

        #pragma unroll
        for (int nt = 0; nt < 4; nt++) {
            int c0 = wn * 32 + nt * 8 + 2 * t;
            float bc0 = __ldg(&b2[c0]), bc1 = __ldg(&b2[c0 + 1]);
            acc[0][nt][0] = gelu_tanh(acc[0][nt][0] + bc0);
            acc[0][nt][1] = gelu_tanh(acc[0][nt][1] + bc1);
            acc[0][nt][2] = gelu_tanh(acc[0][nt][2] + bc0);
            acc[0][nt][3] = gelu_tanh(acc[0][nt][3] + bc1);
            acc[1][nt][0] = gelu_tanh(acc[1][nt][0] + bc0);
            acc[1][nt][1] = gelu_tanh(acc[1][nt][1] + bc1);
            acc[1][nt][2] = gelu_tanh(acc[1][nt][2] + bc0);
            acc[1][nt][3] = gelu_tanh(acc[1][nt][3] + bc1);
        }

        // ---- alpha partials over this warp's 32 cols; reduce over t-lanes ----
        {
            float pa[2][2][2];   // [mt][p][h]
            #pragma unroll
            for (int mt = 0; mt < 2; mt++)
                #pragma unroll
                for (int p = 0; p < 2; p++) { pa[mt][p][0] = 0.f; pa[mt][p][1] = 0.f; }
            #pragma unroll
            for (int mt = 0; mt < 2; mt++)
                #pragma unroll
                for (int nt = 0; nt < 4; nt++) {
                    #pragma unroll
                    for (int h = 0; h < 2; h++) {
                        pa[mt][0][h] += acc[mt][nt][0] * wtp[h][nt].x
                                      + acc[mt][nt][1] * wtp[h][nt].y;
                        pa[mt][1][h] += acc[mt][nt][2] * wtp[h][nt].x
                                      + acc[mt][nt][3] * wtp[h][nt].y;
                    }
                }
            #pragma unroll
            for (int mt = 0; mt < 2; mt++)
                #pragma unroll
                for (int p = 0; p < 2; p++)
                    #pragma unroll
                    for (int h = 0; h < 2; h++) {
                        float v = pa[mt][p][h];
                        v += __shfl_xor_sync(0xffffffffu, v, 1);
                        v += __shfl_xor_sync(0xffffffffu, v, 2);
                        pa[mt][p][h] = v;
                    }
            if (t == 0) {
                #pragma unroll
                for (int mt = 0; mt < 2; mt++)
                    #pragma unroll
                    for (int p = 0; p < 2; p++) {
                        int r = wm * 32 + mt * 16 + g + 8 * p;
                        *(float2*)&sAp[r * 12 + wn * 2] =
                            make_float2(pa[mt][p][0], pa[mt][p][1]);
                    }
            }
        }
        GBAR();                               // bar3: sAp visible

        // ---- finish alpha, form m partials, reduce over g, atomics ----
        {
            float al[2][2][2];   // [mt][p][h]
            #pragma unroll
            for (int mt = 0; mt < 2; mt++)
                #pragma unroll
                for (int p = 0; p < 2; p++) {
                    int r = wm * 32 + mt * 16 + g + 8 * p;
                    float2 f0 = *(const float2*)&sAp[r * 12 + 0];
                    float2 f1 = *(const float2*)&sAp[r * 12 + 2];
                    float2 f2 = *(const float2*)&sAp[r * 12 + 4];
                    float2 f3 = *(const float2*)&sAp[r * 12 + 6];
                    al[mt][p][0] = f0.x + f1.x + f2.x + f3.x + cc0;
                    al[mt][p][1] = f0.y + f1.y + f2.y + f3.y + cc1;
                }
            float pm[2][4][2];   // [h][nt][e]
            #pragma unroll
            for (int h = 0; h < 2; h++)
                #pragma unroll
                for (int nt = 0; nt < 4; nt++) {
                    pm[h][nt][0] = al[0][0][h] * acc[0][nt][0] + al[0][1][h] * acc[0][nt][2]
                                 + al[1][0][h] * acc[1][nt][0] + al[1][1][h] * acc[1][nt][2];
                    pm[h][nt][1] = al[0][0][h] * acc[0][nt][1] + al[0][1][h] * acc[0][nt][3]
                                 + al[1][0][h] * acc[1][nt][1] + al[1][1][h] * acc[1][nt][3];
                }
            #pragma unroll
            for (int h = 0; h < 2; h++)
                #pragma unroll
                for (int nt = 0; nt < 4; nt++)
                    #pragma unroll
                    for (int e = 0; e < 2; e++) {
                        float v = pm[h][nt][e];
                        v += __shfl_xor_sync(0xffffffffu, v, 4);
                        v += __shfl_xor_sync(0xffffffffu, v, 8);
                        v += __shfl_xor_sync(0xffffffffu, v, 16);
                        pm[h][nt][e] = v;
                    }
            if (g == 0) {
                #pragma unroll
                for (int h = 0; h < 2; h++)
                    #pragma unroll
                    for (int nt = 0; nt < 4; nt++)
                        #pragma unroll
                        for (int e = 0; e < 2; e++)
                            atomicAdd(&g_m[b * 256 + h * 128 + wn * 32 + nt * 8 + 2 * t + e],
                                      pm[h][nt][e]);
            }
            // abar: wn==0 warps (wm 0,1) cover all 64 rows exactly once
            if (wn == 0) {
                float s0 = al[0][0][0] + al[0][1][0] + al[1][0][0] + al[1][1][0];
                float s1 = al[0][0][1] + al[0][1][1] + al[1][0][1] + al[1][1][1];
                s0 += __shfl_xor_sync(0xffffffffu, s0, 4);
                s0 += __shfl_xor_sync(0xffffffffu, s0, 8);
                s0 += __shfl_xor_sync(0xffffffffu, s0, 16);
                s1 += __shfl_xor_sync(0xffffffffu, s1, 4);
                s1 += __shfl_xor_sync(0xffffffffu, s1, 8);
                s1 += __shfl_xor_sync(0xffffffffu, s1, 16);
                if (lane == 0) {
                    atomicAdd(&g_ab[b * 2 + 0], s0);
                    atomicAdd(&g_ab[b * 2 + 1], s1);
                }
            }
        }
        tile = nxt;
    }

    // ======== Exit protocol + distributed epilogue ========
    __syncthreads();   // join both groups
    if (tid == 0) { __threadfence(); sPrev = atomicAdd(&g_done, 1); }
    __syncthreads();
    int rank = sPrev;
    if (rank < EPI_RANK0) return;
    if (tid == 0) { while (atomicAdd(&g_done, 0) != GRID_MAIN) __nanosleep(64); }
    __syncthreads();
    __threadfence();

    int bb = rank - EPI_RANK0;   // 0..31, unique per epilogue block
    if (tid < 256) e_m[tid] = g_m[bb * 256 + tid];
    if (tid < 2) e_ab[tid] = g_ab[bb * 2 + tid];
    __syncthreads();
    if (tid < 256) g_m[bb * 256 + tid] = 0.f;   // restore for next replay
    if (tid < 2) g_ab[bb * 2 + tid] = 0.f;

    {   // ov[j] = (abar[h]*bv[j] + m[h][:] . Wv[:,j]) / N
        int j = tid & 127, q = tid >> 7, h = j >> 6;
        float p = 0.f;
        #pragma unroll 4
        for (int pp = q * 32; pp < q * 32 + 32; pp++)
            p += e_m[h * 128 + pp] * __ldg(&Wv[pp * 128 + j]);
        e_p[tid] = p;
    }
    __syncthreads();
    if (tid < 128) {
        int h = tid >> 6;
        e_ov[tid] = (e_p[tid] + e_p[128 + tid] + e_p[256 + tid] + e_p[384 + tid]
                     + e_ab[h] * bv[tid]) * (1.0f / N_);
    }
    __syncthreads();
    {   // out[j] = bo[j] + ov . Wo[:,j]
        int j = tid & 127, q = tid >> 7;
        float p = 0.f;
        #pragma unroll 4
        for (int pp = q * 32; pp < q * 32 + 32; pp++)
            p += e_ov[pp] * __ldg(&Wo[pp * 128 + j]);
        e_p[tid] = p;
    }
    __syncthreads();
    if (tid < 128)
        out[bb * 128 + tid] = e_p[tid] + e_p[128 + tid] + e_p[256 + tid]
                              + e_p[384 + tid] + bo[tid];

    if (tid == 0) {
        __threadfence();
        atomicAdd(&g_done2, 1);
        if (rank == GRID_MAIN - 1) {
            while (atomicAdd(&g_done2, 0) != EPI_BLOCKS) __nanosleep(64);
            g_tile = 0; g_done = 0; g_done2 = 0;
        }
    }
#undef GBAR
}

// ---------------------------------------------------------------------------
extern "C" void kernel_launch(void* const* d_in, const int* in_sizes, int n_in,
                              void* d_out, int out_size) {
    const float* u     = (const float*)d_in[0];
    // d_in[1] = x : unused by the reference
    const float* W1    = (const float*)d_in[2];
    const float* b1    = (const float*)d_in[3];
    const float* W2    = (const float*)d_in[4];
    const float* b2    = (const float*)d_in[5];
    const float* embed = (const float*)d_in[6];
    const float* Wq    = (const float*)d_in[7];
    const float* bq    = (const float*)d_in[8];
    const float* Wk    = (const float*)d_in[9];
    const float* bk    = (const float*)d_in[10];
    const float* Wv    = (const float*)d_in[11];
    const float* bv    = (const float*)d_in[12];
    const float* Wo    = (const float*)d_in[13];
    const float* bo    = (const float*)d_in[14];
    float* out = (float*)d_out;

    const size_t smem_bytes = (size_t)SMEM_FLOATS * sizeof(float);  // 109,600 B
    cudaFuncSetAttribute(main_kernel, cudaFuncAttributeMaxDynamicSharedMemorySize,
                         (int)smem_bytes);

    main_kernel<<<GRID_MAIN, 512, smem_bytes>>>(
        u, W1, b1, W2, b2, embed, Wq, bq, Wk, bk, Wv, bv, Wo, bo, out);
}

// round 16
// speedup vs baseline: 4.0100x; 1.0448x over previous
#include <cuda_runtime.h>
#include <cuda_fp16.h>

#define B_ 32
#define N_ 4096
#define DU_ 64
#define TROWS 64
#define NTOT2 (B_ * 64)           // 2048 tiles of 64 rows
#define GRID_MAIN 148
#define EPI_BLOCKS 32
#define EPI_RANK0 (GRID_MAIN - EPI_BLOCKS)

// Globals (zero at load; every replay restores them to zero)
__device__ float g_m[B_ * 256];   // moment accumulators [b][h*128+j]
__device__ float g_ab[B_ * 2];    // alpha-sum accumulators
__device__ int   g_tile;
__device__ int   g_done;
__device__ int   g_done2;

__device__ __forceinline__ float tanh_fast(float x) {
    float y; asm("tanh.approx.f32 %0, %1;" : "=f"(y) : "f"(x)); return y;
}
__device__ __forceinline__ float gelu_tanh(float x) {
    const float k0 = 0.7978845608028654f;
    float inner = k0 * (x + 0.044715f * x * x * x);
    return 0.5f * x * (1.0f + tanh_fast(inner));
}
__device__ __forceinline__ unsigned pk16(float a, float b) {
    __half2 h = __floats2half2_rn(a, b);
    return *(unsigned*)&h;
}

// fp16 mma: D(16x8,f32) += A(16x16,f16) x B(16x8,f16)
__device__ __forceinline__ void mma16(float* c, const unsigned* a, unsigned b0, unsigned b1) {
    asm volatile(
        "mma.sync.aligned.m16n8k16.row.col.f32.f16.f16.f32 "
        "{%0,%1,%2,%3}, {%4,%5,%6,%7}, {%8,%9}, {%0,%1,%2,%3};\n"
        : "+f"(c[0]), "+f"(c[1]), "+f"(c[2]), "+f"(c[3])
        : "r"(a[0]), "r"(a[1]), "r"(a[2]), "r"(a[3]), "r"(b0), "r"(b1));
}

__device__ __forceinline__ void ldsm4(unsigned* r, unsigned addr) {
    asm volatile("ldmatrix.sync.aligned.m8n8.x4.shared.b16 {%0,%1,%2,%3}, [%4];"
                 : "=r"(r[0]), "=r"(r[1]), "=r"(r[2]), "=r"(r[3]) : "r"(addr));
}

// ---------------------------------------------------------------------------
// SMEM layout (32-bit word units). fp16 operands packed 2-per-word along K.
// A regions: word strides 36/68 (= 4 mod 32) -> LDSM row addresses hit
// disjoint 4-word bank groups: conflict-free. B in FRAGMENT ORDER, stride 8
// + XOR swizzle (conflict-free LDS.64). Per-group sAp stride 12.
// sU is DOUBLE-BUFFERED (2 x 2304 words per group) -> 2 barriers per tile.
// ---------------------------------------------------------------------------
#define OFF_B1   0        // 4w x 4s x 256 = 4096
#define OFF_B2   4096     // 4w x 8s x 256 = 8192 -> 12288
#define OFF_U0   12288    // 2 x (64 x 36) = 4608 -> 16896
#define OFF_U1   16896    // -> 21504
#define OFF_Z0   21504    // 64 x 68 = 4352 -> 25856
#define OFF_Z1G  25856    // -> 30208
#define OFF_WT   30208    // 256 wt + 2 c (+pad 6) -> 30472
#define OFF_AP0  30472    // 64 x 12 = 768 -> 31240
#define OFF_AP1  31240    // -> 32008
#define SMEM_FLOATS 32008 // 128,032 bytes
// sQ (prologue scratch, 640 floats) aliases OFF_Z0.

template<int KSTEPS>
__device__ __forceinline__ void gemm16L(unsigned a0addr, unsigned a1addr,
                                        const unsigned* __restrict__ Bw,
                                        float acc[2][4][4], int lane, int xv) {
    unsigned a[2][2][4];
    uint2 bp[2][4];
    ldsm4(a[0][0], a0addr);
    ldsm4(a[0][1], a1addr);
    {
        const unsigned* bl = Bw + lane * 8;
        #pragma unroll
        for (int nt = 0; nt < 4; nt++) bp[0][nt] = *(const uint2*)&bl[(nt ^ xv) * 2];
    }
    #pragma unroll
    for (int s = 0; s < KSTEPS; s++) {
        int cur = s & 1, nx = cur ^ 1;
        if (s + 1 < KSTEPS) {
            ldsm4(a[nx][0], a0addr + (s + 1) * 32);
            ldsm4(a[nx][1], a1addr + (s + 1) * 32);
            const unsigned* bl = Bw + (s + 1) * 256 + lane * 8;
            #pragma unroll
            for (int nt = 0; nt < 4; nt++) bp[nx][nt] = *(const uint2*)&bl[(nt ^ xv) * 2];
        }
        #pragma unroll
        for (int nt = 0; nt < 4; nt++) {
            mma16(acc[0][nt], a[cur][0], bp[cur][nt].x, bp[cur][nt].y);
            mma16(acc[1][nt], a[cur][1], bp[cur][nt].x, bp[cur][nt].y);
        }
    }
}

// ---------------------------------------------------------------------------
// Single persistent kernel. grid = 148 x 512 threads = 2 independent groups
// of 8 warps (2m x 4n over a 64x128 tile). 2 group barriers per tile.
// ---------------------------------------------------------------------------
__global__ __launch_bounds__(512, 1)
void main_kernel(const float* __restrict__ u,
                 const float* __restrict__ W1, const float* __restrict__ b1,
                 const float* __restrict__ W2, const float* __restrict__ b2,
                 const float* __restrict__ embed,
                 const float* __restrict__ Wq, const float* __restrict__ bq,
                 const float* __restrict__ Wk, const float* __restrict__ bk,
                 const float* __restrict__ Wv, const float* __restrict__ bv,
                 const float* __restrict__ Wo, const float* __restrict__ bo,
                 float* __restrict__ out) {
    extern __shared__ float sm[];
    unsigned* sB1u = (unsigned*)(sm + OFF_B1);
    unsigned* sB2u = (unsigned*)(sm + OFF_B2);
    float* sWT = sm + OFF_WT;
    float* sQ  = sm + OFF_Z0;   // prologue scratch

    __shared__ int sTile[2];
    __shared__ int sPrev;
    __shared__ float e_m[256], e_ab[2], e_ov[128], e_p[512];

    const int tid = threadIdx.x;
    const int lane = tid & 31, warp = tid >> 5;
    const int grp = warp >> 3;                 // 0 or 1
    const int lt = tid & 255;                  // id within group
    const int w8 = warp & 7;
    const int wm = w8 & 1, wn = w8 >> 1;       // 2m x 4n, warp tile 32x32
    const int g = lane >> 2, t = lane & 3;
    const int xv = g & 3;
    const int barid = grp + 1;

    unsigned shbase;
    { unsigned long long tmp;
      asm("cvta.to.shared.u64 %0, %1;" : "=l"(tmp) : "l"((const void*)sm));
      shbase = (unsigned)tmp; }

    const int baseU = grp ? OFF_U1 : OFF_U0;
    unsigned* sU16base = (unsigned*)(sm + baseU);
    unsigned* sZ1u = (unsigned*)(sm + (grp ? OFF_Z1G : OFF_Z0));
    float* sAp = sm + (grp ? OFF_AP1 : OFF_AP0);
    const unsigned ubyte0 = shbase + (unsigned)baseU * 4u;
    const unsigned zbyte  = shbase + (unsigned)(grp ? OFF_Z1G : OFF_Z0) * 4u;

    // LDSM per-lane address offsets
    const int q = lane >> 3, rr = lane & 7;
    const int arow = wm * 32 + rr + ((q & 1) << 3);
    const int akoff = (q >> 1) * 4;  // words
    const unsigned offU0 = (unsigned)((arow * 36 + akoff) * 4);
    const unsigned offU1 = offU0 + 16u * 36u * 4u;
    const unsigned zA0 = zbyte + (unsigned)((arow * 68 + akoff) * 4);
    const unsigned zA1 = zA0 + 16u * 68u * 4u;

#define GBAR() asm volatile("bar.sync %0, 256;" :: "r"(barid) : "memory")

    // ======== Prologue A: pack W1/W2 into fp16 fragment order ========
    #pragma unroll 2
    for (int idx = tid; idx < 2048; idx += 512) {   // W1: 4w x 4s x 32l x 4nt
        int nt = idx & 3, ln = (idx >> 2) & 31, s = (idx >> 7) & 3, w = idx >> 9;
        int tt = ln & 3, gg = ln >> 2;
        int n = w * 32 + nt * 8 + gg;
        int k0 = s * 16 + 2 * tt;
        unsigned* d = &sB1u[(w * 4 + s) * 256 + ln * 8 + ((nt ^ (gg & 3)) * 2)];
        d[0] = pk16(W1[k0 * 128 + n],       W1[(k0 + 1) * 128 + n]);
        d[1] = pk16(W1[(k0 + 8) * 128 + n], W1[(k0 + 9) * 128 + n]);
    }
    #pragma unroll 2
    for (int idx = tid; idx < 4096; idx += 512) {   // W2: 4w x 8s x 32l x 4nt
        int nt = idx & 3, ln = (idx >> 2) & 31, s = (idx >> 7) & 7, w = idx >> 10;
        int tt = ln & 3, gg = ln >> 2;
        int n = w * 32 + nt * 8 + gg;
        int k0 = s * 16 + 2 * tt;
        unsigned* d = &sB2u[(w * 8 + s) * 256 + ln * 8 + ((nt ^ (gg & 3)) * 2)];
        d[0] = pk16(W2[k0 * 128 + n],       W2[(k0 + 1) * 128 + n]);
        d[1] = pk16(W2[(k0 + 8) * 128 + n], W2[(k0 + 9) * 128 + n]);
    }

    // ======== Prologue B: q, w~, c ========
    if (tid < 256) {
        int j = tid & 127, half = tid >> 7;
        float p = 0.f;
        #pragma unroll 4
        for (int i = half * 64; i < half * 64 + 64; i++) p += embed[i] * Wq[i * 128 + j];
        sQ[half * 128 + j] = p;
    }
    __syncthreads();
    if (tid < 128) sQ[256 + tid] = bq[tid] + sQ[tid] + sQ[128 + tid];
    __syncthreads();
    if (tid < 256) {
        int h = tid >> 7, i = tid & 127;
        const float* qh = &sQ[256 + h * 64];
        const float* wk = &Wk[i * 128 + h * 64];
        float s0 = 0.f, s1 = 0.f, s2 = 0.f, s3 = 0.f;
        #pragma unroll 8
        for (int d = 0; d < 64; d += 4) {
            s0 += wk[d] * qh[d];         s1 += wk[d + 1] * qh[d + 1];
            s2 += wk[d + 2] * qh[d + 2]; s3 += wk[d + 3] * qh[d + 3];
        }
        sWT[tid] = (s0 + s1) + (s2 + s3);
    }
    if (tid < 2) {
        const float* qh = &sQ[256 + tid * 64];
        float s = 0.f;
        #pragma unroll 8
        for (int d = 0; d < 64; d++) s += bk[tid * 64 + d] * qh[d];
        sWT[256 + tid] = s;
    }
    __syncthreads();

    // persistent per-thread constants
    float2 wtp[2][4];
    #pragma unroll
    for (int h = 0; h < 2; h++)
        #pragma unroll
        for (int nt = 0; nt < 4; nt++)
            wtp[h][nt] = *(const float2*)&sWT[h * 128 + wn * 32 + nt * 8 + 2 * t];
    const float cc0 = sWT[256], cc1 = sWT[257];

    if (lt == 0) sTile[grp] = atomicAdd(&g_tile, 1);
    __syncthreads();   // sQ dead (aliased group-0 Z1); tickets visible
    int tile = sTile[grp];

    // stage first u tile into buffer 0
    float4 up[4];
    if (tile < NTOT2) {
        int bb = tile >> 6, r0 = (tile & 63) * TROWS;
        const float4* src = (const float4*)(u + ((size_t)bb * N_ + r0) * DU_);
        #pragma unroll
        for (int it = 0; it < 4; it++) up[it] = src[lt + it * 256];
        #pragma unroll
        for (int it = 0; it < 4; it++) {
            int i = lt + it * 256;
            int r = i >> 4, c2 = (i & 15) * 2;
            uint2 v;
            v.x = pk16(up[it].x, up[it].y);
            v.y = pk16(up[it].z, up[it].w);
            *(uint2*)&sU16base[r * 36 + c2] = v;
        }
    }
    if (lt == 0) sTile[grp] = atomicAdd(&g_tile, 1);
    GBAR();
    int nxt = sTile[grp];
    int c = 0;

    // ======== Persistent per-group tile loop (2 named barriers) ========
    while (tile < NTOT2) {
        const int b = tile >> 6;
        const unsigned uA = ubyte0 + (unsigned)(c * 9216);   // 2304 words

        // ---- Stage 1: Z1 = gelu(U @ W1 + b1), K=64 (4 ksteps) ----
        float acc[2][4][4];
        #pragma unroll
        for (int mt = 0; mt < 2; mt++)
            #pragma unroll
            for (int nt = 0; nt < 4; nt++)
                #pragma unroll
                for (int e = 0; e < 4; e++) acc[mt][nt][e] = 0.f;

        gemm16L<4>(uA + offU0, uA + offU1, sB1u + wn * (4 * 256), acc, lane, xv);

        #pragma unroll
        for (int nt = 0; nt < 4; nt++) {
            int c0 = wn * 32 + nt * 8 + 2 * t;
            float bc0 = __ldg(&b1[c0]), bc1 = __ldg(&b1[c0 + 1]);
            int wi = c0 >> 1;   // packed word index
            #pragma unroll
            for (int mt = 0; mt < 2; mt++) {
                int r = wm * 32 + mt * 16 + g;
                sZ1u[r * 68 + wi] =
                    pk16(gelu_tanh(acc[mt][nt][0] + bc0), gelu_tanh(acc[mt][nt][1] + bc1));
                sZ1u[(r + 8) * 68 + wi] =
                    pk16(gelu_tanh(acc[mt][nt][2] + bc0), gelu_tanh(acc[mt][nt][3] + bc1));
            }
        }
        GBAR();                               // bar2: sZ1 visible

        // prefetch u(nxt); LDG latency hides behind gemm2
        if (nxt < NTOT2) {
            int bb = nxt >> 6, r0 = (nxt & 63) * TROWS;
            const float4* src = (const float4*)(u + ((size_t)bb * N_ + r0) * DU_);
            #pragma unroll
            for (int it = 0; it < 4; it++) up[it] = src[lt + it * 256];
        }

        // ---- Stage 2: Z2 = gelu(Z1 @ W2 + b2), K=128 (8 ksteps; regs) ----
        #pragma unroll
        for (int mt = 0; mt < 2; mt++)
            #pragma unroll
            for (int nt = 0; nt < 4; nt++)
                #pragma unroll
                for (int e = 0; e < 4; e++) acc[mt][nt][e] = 0.f;

        gemm16L<8>(zA0, zA1, sB2u + wn * (8 * 256), acc, lane, xv);

        // stage u(nxt) into the other buffer (published by bar3)
        if (nxt < NTOT2) {
            unsigned* dstU = sU16base + (c ^ 1) * 2304;
            #pragma unroll
            for (int it = 0; it < 4; it++) {
                int i = lt + it * 256;
                int r = i >> 4, c2 = (i & 15) * 2;
                uint2 v;
                v.x = pk16(up[it].x, up[it].y);
                v.y = pk16(up[it].z, up[it].w);
                *(uint2*)&dstU[r * 36 + c2] = v;
            }
        }

        #pragma unroll
        for (int nt = 0; nt < 4; nt++) {
            int c0 = wn * 32 + nt * 8 + 2 * t;
            float bc0 = __ldg(&b2[c0]), bc1 = __ldg(&b2[c0 + 1]);
            acc[0][nt][0] = gelu_tanh(acc[0][nt][0] + bc0);
            acc[0][nt][1] = gelu_tanh(acc[0][nt][1] + bc1);
            acc[0][nt][2] = gelu_tanh(acc[0][nt][2] + bc0);
            acc[0][nt][3] = gelu_tanh(acc[0][nt][3] + bc1);
            acc[1][nt][0] = gelu_tanh(acc[1][nt][0] + bc0);
            acc[1][nt][1] = gelu_tanh(acc[1][nt][1] + bc1);
            acc[1][nt][2] = gelu_tanh(acc[1][nt][2] + bc0);
            acc[1][nt][3] = gelu_tanh(acc[1][nt][3] + bc1);
        }

        // ---- alpha partials over this warp's 32 cols; reduce over t-lanes ----
        {
            float pa[2][2][2];   // [mt][p][h]
            #pragma unroll
            for (int mt = 0; mt < 2; mt++)
                #pragma unroll
                for (int p = 0; p < 2; p++) { pa[mt][p][0] = 0.f; pa[mt][p][1] = 0.f; }
            #pragma unroll
            for (int mt = 0; mt < 2; mt++)
                #pragma unroll
                for (int nt = 0; nt < 4; nt++) {
                    #pragma unroll
                    for (int h = 0; h < 2; h++) {
                        pa[mt][0][h] += acc[mt][nt][0] * wtp[h][nt].x
                                      + acc[mt][nt][1] * wtp[h][nt].y;
                        pa[mt][1][h] += acc[mt][nt][2] * wtp[h][nt].x
                                      + acc[mt][nt][3] * wtp[h][nt].y;
                    }
                }
            #pragma unroll
            for (int mt = 0; mt < 2; mt++)
                #pragma unroll
                for (int p = 0; p < 2; p++)
                    #pragma unroll
                    for (int h = 0; h < 2; h++) {
                        float v = pa[mt][p][h];
                        v += __shfl_xor_sync(0xffffffffu, v, 1);
                        v += __shfl_xor_sync(0xffffffffu, v, 2);
                        pa[mt][p][h] = v;
                    }
            if (t == 0) {
                #pragma unroll
                for (int mt = 0; mt < 2; mt++)
                    #pragma unroll
                    for (int p = 0; p < 2; p++) {
                        int r = wm * 32 + mt * 16 + g + 8 * p;
                        *(float2*)&sAp[r * 12 + wn * 2] =
                            make_float2(pa[mt][p][0], pa[mt][p][1]);
                    }
            }
        }
        if (lt == 0) sTile[grp] = atomicAdd(&g_tile, 1);
        GBAR();                               // bar3: sAp + sU[c^1] + ticket
        int nxt2 = sTile[grp];

        // ---- finish alpha, form m partials, reduce over g, atomics ----
        {
            float al[2][2][2];   // [mt][p][h]
            #pragma unroll
            for (int mt = 0; mt < 2; mt++)
                #pragma unroll
                for (int p = 0; p < 2; p++) {
                    int r = wm * 32 + mt * 16 + g + 8 * p;
                    float2 f0 = *(const float2*)&sAp[r * 12 + 0];
                    float2 f1 = *(const float2*)&sAp[r * 12 + 2];
                    float2 f2 = *(const float2*)&sAp[r * 12 + 4];
                    float2 f3 = *(const float2*)&sAp[r * 12 + 6];
                    al[mt][p][0] = f0.x + f1.x + f2.x + f3.x + cc0;
                    al[mt][p][1] = f0.y + f1.y + f2.y + f3.y + cc1;
                }
            float pm[2][4][2];   // [h][nt][e]
            #pragma unroll
            for (int h = 0; h < 2; h++)
                #pragma unroll
                for (int nt = 0; nt < 4; nt++) {
                    pm[h][nt][0] = al[0][0][h] * acc[0][nt][0] + al[0][1][h] * acc[0][nt][2]
                                 + al[1][0][h] * acc[1][nt][0] + al[1][1][h] * acc[1][nt][2];
                    pm[h][nt][1] = al[0][0][h] * acc[0][nt][1] + al[0][1][h] * acc[0][nt][3]
                                 + al[1][0][h] * acc[1][nt][1] + al[1][1][h] * acc[1][nt][3];
                }
            #pragma unroll
            for (int h = 0; h < 2; h++)
                #pragma unroll
                for (int nt = 0; nt < 4; nt++)
                    #pragma unroll
                    for (int e = 0; e < 2; e++) {
                        float v = pm[h][nt][e];
                        v += __shfl_xor_sync(0xffffffffu, v, 4);
                        v += __shfl_xor_sync(0xffffffffu, v, 8);
                        v += __shfl_xor_sync(0xffffffffu, v, 16);
                        pm[h][nt][e] = v;
                    }
            if (g == 0) {
                #pragma unroll
                for (int h = 0; h < 2; h++)
                    #pragma unroll
                    for (int nt = 0; nt < 4; nt++)
                        #pragma unroll
                        for (int e = 0; e < 2; e++)
                            atomicAdd(&g_m[b * 256 + h * 128 + wn * 32 + nt * 8 + 2 * t + e],
                                      pm[h][nt][e]);
            }
            // abar: wn==0 warps (wm 0,1) cover all 64 rows exactly once
            if (wn == 0) {
                float s0 = al[0][0][0] + al[0][1][0] + al[1][0][0] + al[1][1][0];
                float s1 = al[0][0][1] + al[0][1][1] + al[1][0][1] + al[1][1][1];
                s0 += __shfl_xor_sync(0xffffffffu, s0, 4);
                s0 += __shfl_xor_sync(0xffffffffu, s0, 8);
                s0 += __shfl_xor_sync(0xffffffffu, s0, 16);
                s1 += __shfl_xor_sync(0xffffffffu, s1, 4);
                s1 += __shfl_xor_sync(0xffffffffu, s1, 8);
                s1 += __shfl_xor_sync(0xffffffffu, s1, 16);
                if (lane == 0) {
                    atomicAdd(&g_ab[b * 2 + 0], s0);
                    atomicAdd(&g_ab[b * 2 + 1], s1);
                }
            }
        }
        tile = nxt;
        nxt = nxt2;
        c ^= 1;
    }

    // ======== Exit protocol + distributed epilogue ========
    __syncthreads();   // join both groups
    if (tid == 0) { __threadfence(); sPrev = atomicAdd(&g_done, 1); }
    __syncthreads();
    int rank = sPrev;
    if (rank < EPI_RANK0) return;
    if (tid == 0) { while (atomicAdd(&g_done, 0) != GRID_MAIN) __nanosleep(64); }
    __syncthreads();
    __threadfence();

    int bb = rank - EPI_RANK0;   // 0..31, unique per epilogue block
    if (tid < 256) e_m[tid] = g_m[bb * 256 + tid];
    if (tid < 2) e_ab[tid] = g_ab[bb * 2 + tid];
    __syncthreads();
    if (tid < 256) g_m[bb * 256 + tid] = 0.f;   // restore for next replay
    if (tid < 2) g_ab[bb * 2 + tid] = 0.f;

    {   // ov[j] = (abar[h]*bv[j] + m[h][:] . Wv[:,j]) / N
        int j = tid & 127, qq = tid >> 7, h = j >> 6;
        float p = 0.f;
        #pragma unroll 4
        for (int pp = qq * 32; pp < qq * 32 + 32; pp++)
            p += e_m[h * 128 + pp] * __ldg(&Wv[pp * 128 + j]);
        e_p[tid] = p;
    }
    __syncthreads();
    if (tid < 128) {
        int h = tid >> 6;
        e_ov[tid] = (e_p[tid] + e_p[128 + tid] + e_p[256 + tid] + e_p[384 + tid]
                     + e_ab[h] * bv[tid]) * (1.0f / N_);
    }
    __syncthreads();
    {   // out[j] = bo[j] + ov . Wo[:,j]
        int j = tid & 127, qq = tid >> 7;
        float p = 0.f;
        #pragma unroll 4
        for (int pp = qq * 32; pp < qq * 32 + 32; pp++)
            p += e_ov[pp] * __ldg(&Wo[pp * 128 + j]);
        e_p[tid] = p;
    }
    __syncthreads();
    if (tid < 128)
        out[bb * 128 + tid] = e_p[tid] + e_p[128 + tid] + e_p[256 + tid]
                              + e_p[384 + tid] + bo[tid];

    if (tid == 0) {
        __threadfence();
        atomicAdd(&g_done2, 1);
        if (rank == GRID_MAIN - 1) {
            while (atomicAdd(&g_done2, 0) != EPI_BLOCKS) __nanosleep(64);
            g_tile = 0; g_done = 0; g_done2 = 0;
        }
    }
#undef GBAR
}

// ---------------------------------------------------------------------------
extern "C" void kernel_launch(void* const* d_in, const int* in_sizes, int n_in,
                              void* d_out, int out_size) {
    const float* u     = (const float*)d_in[0];
    // d_in[1] = x : unused by the reference
    const float* W1    = (const float*)d_in[2];
    const float* b1    = (const float*)d_in[3];
    const float* W2    = (const float*)d_in[4];
    const float* b2    = (const float*)d_in[5];
    const float* embed = (const float*)d_in[6];
    const float* Wq    = (const float*)d_in[7];
    const float* bq    = (const float*)d_in[8];
    const float* Wk    = (const float*)d_in[9];
    const float* bk    = (const float*)d_in[10];
    const float* Wv    = (const float*)d_in[11];
    const float* bv    = (const float*)d_in[12];
    const float* Wo    = (const float*)d_in[13];
    const float* bo    = (const float*)d_in[14];
    float* out = (float*)d_out;

    const size_t smem_bytes = (size_t)SMEM_FLOATS * sizeof(float);  // 128,032 B
    cudaFuncSetAttribute(main_kernel, cudaFuncAttributeMaxDynamicSharedMemorySize,
                         (int)smem_bytes);

    main_kernel<<<GRID_MAIN, 512, smem_bytes>>>(
        u, W1, b1, W2, b2, embed, Wq, bq, Wk, bk, Wv, bv, Wo, bo, out);
}

// round 17
// speedup vs baseline: 4.4729x; 1.1154x over previous
#include <cuda_runtime.h>
#include <cuda_fp16.h>

#define B_ 32
#define N_ 4096
#define DU_ 64
#define TROWS 32
#define NTOT4 (B_ * 128)          // 4096 tiles of 32 rows
#define GRID_MAIN 148
#define EPI_BLOCKS 32
#define EPI_RANK0 (GRID_MAIN - EPI_BLOCKS)

// Globals (zero at load; every replay restores them to zero)
__device__ float g_m[B_ * 256];   // moment accumulators [b][h*128+j]
__device__ float g_ab[B_ * 2];    // alpha-sum accumulators
__device__ int   g_tile;
__device__ int   g_done;
__device__ int   g_done2;

__device__ __forceinline__ float tanh_fast(float x) {
    float y; asm("tanh.approx.f32 %0, %1;" : "=f"(y) : "f"(x)); return y;
}
__device__ __forceinline__ float gelu_tanh(float x) {
    const float k0 = 0.7978845608028654f;
    float inner = k0 * (x + 0.044715f * x * x * x);
    return 0.5f * x * (1.0f + tanh_fast(inner));
}
__device__ __forceinline__ unsigned pk16(float a, float b) {
    __half2 h = __floats2half2_rn(a, b);
    return *(unsigned*)&h;
}

// fp16 mma: D(16x8,f32) += A(16x16,f16) x B(16x8,f16)
__device__ __forceinline__ void mma16(float* c, const unsigned* a, unsigned b0, unsigned b1) {
    asm volatile(
        "mma.sync.aligned.m16n8k16.row.col.f32.f16.f16.f32 "
        "{%0,%1,%2,%3}, {%4,%5,%6,%7}, {%8,%9}, {%0,%1,%2,%3};\n"
        : "+f"(c[0]), "+f"(c[1]), "+f"(c[2]), "+f"(c[3])
        : "r"(a[0]), "r"(a[1]), "r"(a[2]), "r"(a[3]), "r"(b0), "r"(b1));
}

__device__ __forceinline__ void ldsm4(unsigned* r, unsigned addr) {
    asm volatile("ldmatrix.sync.aligned.m8n8.x4.shared.b16 {%0,%1,%2,%3}, [%4];"
                 : "=r"(r[0]), "=r"(r[1]), "=r"(r[2]), "=r"(r[3]) : "r"(addr));
}

// ---------------------------------------------------------------------------
// SMEM layout (32-bit word units). fp16 operands packed 2-per-word along K.
// A strides 36/68 words (= 4 mod 32): LDSM rows hit disjoint bank groups,
// conflict-free. B in FRAGMENT ORDER, stride 8 + XOR swizzle (conflict-free
// LDS.64). 4 groups x 4 warps; per-group region: sU dbl-buf 2x1152, sZ1
// 2176, sAp 384 = 4864 words.
// ---------------------------------------------------------------------------
#define OFF_B1   0        // 4w x 4s x 256 = 4096
#define OFF_B2   4096     // 4w x 8s x 256 = 8192 -> 12288
#define OFF_GRP  12288    // 4 x 4864 -> 31744
#define GRP_SZ   4864
#define OFF_WT   31744    // 256 wt + 2 c (+pad 6) -> 32008
#define SMEM_FLOATS 32008 // 128,032 bytes
// sQ (prologue scratch, 640 floats) aliases group-0 sZ1.

template<int KSTEPS>
__device__ __forceinline__ void gemm16L(unsigned a0addr, unsigned a1addr,
                                        const unsigned* __restrict__ Bw,
                                        float acc[2][4][4], int lane, int xv) {
    unsigned a[2][2][4];
    uint2 bp[2][4];
    ldsm4(a[0][0], a0addr);
    ldsm4(a[0][1], a1addr);
    {
        const unsigned* bl = Bw + lane * 8;
        #pragma unroll
        for (int nt = 0; nt < 4; nt++) bp[0][nt] = *(const uint2*)&bl[(nt ^ xv) * 2];
    }
    #pragma unroll
    for (int s = 0; s < KSTEPS; s++) {
        int cur = s & 1, nx = cur ^ 1;
        if (s + 1 < KSTEPS) {
            ldsm4(a[nx][0], a0addr + (s + 1) * 32);
            ldsm4(a[nx][1], a1addr + (s + 1) * 32);
            const unsigned* bl = Bw + (s + 1) * 256 + lane * 8;
            #pragma unroll
            for (int nt = 0; nt < 4; nt++) bp[nx][nt] = *(const uint2*)&bl[(nt ^ xv) * 2];
        }
        #pragma unroll
        for (int nt = 0; nt < 4; nt++) {
            mma16(acc[0][nt], a[cur][0], bp[cur][nt].x, bp[cur][nt].y);
            mma16(acc[1][nt], a[cur][1], bp[cur][nt].x, bp[cur][nt].y);
        }
    }
}

// ---------------------------------------------------------------------------
// Single persistent kernel. grid = 148 x 512 threads = 4 independent groups
// of 4 warps (1m x 4n over a 32x128 tile). Each SMSP hosts one warp from
// each group -> phase-desynced pipe mixing. 2 group barriers per tile.
// ---------------------------------------------------------------------------
__global__ __launch_bounds__(512, 1)
void main_kernel(const float* __restrict__ u,
                 const float* __restrict__ W1, const float* __restrict__ b1,
                 const float* __restrict__ W2, const float* __restrict__ b2,
                 const float* __restrict__ embed,
                 const float* __restrict__ Wq, const float* __restrict__ bq,
                 const float* __restrict__ Wk, const float* __restrict__ bk,
                 const float* __restrict__ Wv, const float* __restrict__ bv,
                 const float* __restrict__ Wo, const float* __restrict__ bo,
                 float* __restrict__ out) {
    extern __shared__ float sm[];
    unsigned* sB1u = (unsigned*)(sm + OFF_B1);
    unsigned* sB2u = (unsigned*)(sm + OFF_B2);
    float* sWT = sm + OFF_WT;
    float* sQ  = sm + OFF_GRP + 2304;   // prologue scratch (group-0 sZ1)

    __shared__ int sTile[4];
    __shared__ int sPrev;
    __shared__ float e_m[256], e_ab[2], e_ov[128], e_p[512];

    const int tid = threadIdx.x;
    const int lane = tid & 31, warp = tid >> 5;
    const int grp = warp >> 2;                 // 0..3
    const int lt = tid & 127;                  // id within group
    const int wn = warp & 3;                   // n-tile 0..3; warp = 32r x 32c
    const int g = lane >> 2, t = lane & 3;
    const int xv = g & 3;
    const int barid = grp + 1;

    unsigned shbase;
    { unsigned long long tmp;
      asm("cvta.to.shared.u64 %0, %1;" : "=l"(tmp) : "l"((const void*)sm));
      shbase = (unsigned)tmp; }

    const int gbase = OFF_GRP + grp * GRP_SZ;
    unsigned* sU16base = (unsigned*)(sm + gbase);          // 2 x 1152 words
    unsigned* sZ1u = (unsigned*)(sm + gbase + 2304);       // 2176 words
    float* sAp = sm + gbase + 2304 + 2176;                 // 384 words
    const unsigned ubyte0 = shbase + (unsigned)gbase * 4u;
    const unsigned zbyte  = shbase + (unsigned)(gbase + 2304) * 4u;

    // LDSM per-lane address offsets (rows 0..15 and 16..31)
    const int q = lane >> 3, rr = lane & 7;
    const int arow = rr + ((q & 1) << 3);
    const int akoff = (q >> 1) * 4;  // words
    const unsigned offU0 = (unsigned)((arow * 36 + akoff) * 4);
    const unsigned offU1 = offU0 + 16u * 36u * 4u;
    const unsigned zA0 = zbyte + (unsigned)((arow * 68 + akoff) * 4);
    const unsigned zA1 = zA0 + 16u * 68u * 4u;

#define GBAR() asm volatile("bar.sync %0, 128;" :: "r"(barid) : "memory")

    // ======== Prologue A: pack W1/W2 into fp16 fragment order ========
    #pragma unroll 2
    for (int idx = tid; idx < 2048; idx += 512) {   // W1: 4w x 4s x 32l x 4nt
        int nt = idx & 3, ln = (idx >> 2) & 31, s = (idx >> 7) & 3, w = idx >> 9;
        int tt = ln & 3, gg = ln >> 2;
        int n = w * 32 + nt * 8 + gg;
        int k0 = s * 16 + 2 * tt;
        unsigned* d = &sB1u[(w * 4 + s) * 256 + ln * 8 + ((nt ^ (gg & 3)) * 2)];
        d[0] = pk16(W1[k0 * 128 + n],       W1[(k0 + 1) * 128 + n]);
        d[1] = pk16(W1[(k0 + 8) * 128 + n], W1[(k0 + 9) * 128 + n]);
    }
    #pragma unroll 2
    for (int idx = tid; idx < 4096; idx += 512) {   // W2: 4w x 8s x 32l x 4nt
        int nt = idx & 3, ln = (idx >> 2) & 31, s = (idx >> 7) & 7, w = idx >> 10;
        int tt = ln & 3, gg = ln >> 2;
        int n = w * 32 + nt * 8 + gg;
        int k0 = s * 16 + 2 * tt;
        unsigned* d = &sB2u[(w * 8 + s) * 256 + ln * 8 + ((nt ^ (gg & 3)) * 2)];
        d[0] = pk16(W2[k0 * 128 + n],       W2[(k0 + 1) * 128 + n]);
        d[1] = pk16(W2[(k0 + 8) * 128 + n], W2[(k0 + 9) * 128 + n]);
    }

    // ======== Prologue B: q, w~, c ========
    if (tid < 256) {
        int j = tid & 127, half = tid >> 7;
        float p = 0.f;
        #pragma unroll 4
        for (int i = half * 64; i < half * 64 + 64; i++) p += embed[i] * Wq[i * 128 + j];
        sQ[half * 128 + j] = p;
    }
    __syncthreads();
    if (tid < 128) sQ[256 + tid] = bq[tid] + sQ[tid] + sQ[128 + tid];
    __syncthreads();
    if (tid < 256) {
        int h = tid >> 7, i = tid & 127;
        const float* qh = &sQ[256 + h * 64];
        const float* wk = &Wk[i * 128 + h * 64];
        float s0 = 0.f, s1 = 0.f, s2 = 0.f, s3 = 0.f;
        #pragma unroll 8
        for (int d = 0; d < 64; d += 4) {
            s0 += wk[d] * qh[d];         s1 += wk[d + 1] * qh[d + 1];
            s2 += wk[d + 2] * qh[d + 2]; s3 += wk[d + 3] * qh[d + 3];
        }
        sWT[tid] = (s0 + s1) + (s2 + s3);
    }
    if (tid < 2) {
        const float* qh = &sQ[256 + tid * 64];
        float s = 0.f;
        #pragma unroll 8
        for (int d = 0; d < 64; d++) s += bk[tid * 64 + d] * qh[d];
        sWT[256 + tid] = s;
    }
    __syncthreads();

    // persistent per-thread constants
    float2 wtp[2][4];
    #pragma unroll
    for (int h = 0; h < 2; h++)
        #pragma unroll
        for (int nt = 0; nt < 4; nt++)
            wtp[h][nt] = *(const float2*)&sWT[h * 128 + wn * 32 + nt * 8 + 2 * t];
    const float cc0 = sWT[256], cc1 = sWT[257];

    if (lt == 0) sTile[grp] = atomicAdd(&g_tile, 1);
    __syncthreads();   // sQ (group-0 sZ1) dead; tickets visible
    int tile = sTile[grp];

    // stage first u tile into buffer 0 (32 rows x 64 cols = 512 float4)
    float4 up[4];
    if (tile < NTOT4) {
        int bb = tile >> 7, r0 = (tile & 127) * TROWS;
        const float4* src = (const float4*)(u + ((size_t)bb * N_ + r0) * DU_);
        #pragma unroll
        for (int it = 0; it < 4; it++) up[it] = src[lt + it * 128];
        #pragma unroll
        for (int it = 0; it < 4; it++) {
            int i = lt + it * 128;
            int r = i >> 4, c2 = (i & 15) * 2;
            uint2 v;
            v.x = pk16(up[it].x, up[it].y);
            v.y = pk16(up[it].z, up[it].w);
            *(uint2*)&sU16base[r * 36 + c2] = v;
        }
    }
    if (lt == 0) sTile[grp] = atomicAdd(&g_tile, 1);
    GBAR();
    int nxt = sTile[grp];
    int c = 0;

    // ======== Persistent per-group tile loop (2 named barriers) ========
    while (tile < NTOT4) {
        const int b = tile >> 7;
        const unsigned uA = ubyte0 + (unsigned)(c * 4608);   // 1152 words

        // loop-top prefetch: LDG u(nxt); consumed after gemm2 (long cover)
        if (nxt < NTOT4) {
            int bb = nxt >> 7, r0 = (nxt & 127) * TROWS;
            const float4* src = (const float4*)(u + ((size_t)bb * N_ + r0) * DU_);
            #pragma unroll
            for (int it = 0; it < 4; it++) up[it] = src[lt + it * 128];
        }

        // ---- Stage 1: Z1 = gelu(U @ W1 + b1), K=64 (4 ksteps) ----
        float acc[2][4][4];
        #pragma unroll
        for (int mt = 0; mt < 2; mt++)
            #pragma unroll
            for (int nt = 0; nt < 4; nt++)
                #pragma unroll
                for (int e = 0; e < 4; e++) acc[mt][nt][e] = 0.f;

        gemm16L<4>(uA + offU0, uA + offU1, sB1u + wn * (4 * 256), acc, lane, xv);

        #pragma unroll
        for (int nt = 0; nt < 4; nt++) {
            int c0 = wn * 32 + nt * 8 + 2 * t;
            float bc0 = __ldg(&b1[c0]), bc1 = __ldg(&b1[c0 + 1]);
            int wi = c0 >> 1;   // packed word index
            #pragma unroll
            for (int mt = 0; mt < 2; mt++) {
                int r = mt * 16 + g;
                sZ1u[r * 68 + wi] =
                    pk16(gelu_tanh(acc[mt][nt][0] + bc0), gelu_tanh(acc[mt][nt][1] + bc1));
                sZ1u[(r + 8) * 68 + wi] =
                    pk16(gelu_tanh(acc[mt][nt][2] + bc0), gelu_tanh(acc[mt][nt][3] + bc1));
            }
        }
        GBAR();                               // bar2: sZ1 visible

        // ---- Stage 2: Z2 = gelu(Z1 @ W2 + b2), K=128 (8 ksteps; regs) ----
        #pragma unroll
        for (int mt = 0; mt < 2; mt++)
            #pragma unroll
            for (int nt = 0; nt < 4; nt++)
                #pragma unroll
                for (int e = 0; e < 4; e++) acc[mt][nt][e] = 0.f;

        gemm16L<8>(zA0, zA1, sB2u + wn * (8 * 256), acc, lane, xv);

        // stage u(nxt) into the other buffer (published by bar3)
        if (nxt < NTOT4) {
            unsigned* dstU = sU16base + (c ^ 1) * 1152;
            #pragma unroll
            for (int it = 0; it < 4; it++) {
                int i = lt + it * 128;
                int r = i >> 4, c2 = (i & 15) * 2;
                uint2 v;
                v.x = pk16(up[it].x, up[it].y);
                v.y = pk16(up[it].z, up[it].w);
                *(uint2*)&dstU[r * 36 + c2] = v;
            }
        }

        #pragma unroll
        for (int nt = 0; nt < 4; nt++) {
            int c0 = wn * 32 + nt * 8 + 2 * t;
            float bc0 = __ldg(&b2[c0]), bc1 = __ldg(&b2[c0 + 1]);
            acc[0][nt][0] = gelu_tanh(acc[0][nt][0] + bc0);
            acc[0][nt][1] = gelu_tanh(acc[0][nt][1] + bc1);
            acc[0][nt][2] = gelu_tanh(acc[0][nt][2] + bc0);
            acc[0][nt][3] = gelu_tanh(acc[0][nt][3] + bc1);
            acc[1][nt][0] = gelu_tanh(acc[1][nt][0] + bc0);
            acc[1][nt][1] = gelu_tanh(acc[1][nt][1] + bc1);
            acc[1][nt][2] = gelu_tanh(acc[1][nt][2] + bc0);
            acc[1][nt][3] = gelu_tanh(acc[1][nt][3] + bc1);
        }

        // ---- alpha partials over this warp's 32 cols; reduce over t-lanes ----
        {
            float pa[2][2][2];   // [mt][p][h]
            #pragma unroll
            for (int mt = 0; mt < 2; mt++)
                #pragma unroll
                for (int p = 0; p < 2; p++) { pa[mt][p][0] = 0.f; pa[mt][p][1] = 0.f; }
            #pragma unroll
            for (int mt = 0; mt < 2; mt++)
                #pragma unroll
                for (int nt = 0; nt < 4; nt++) {
                    #pragma unroll
                    for (int h = 0; h < 2; h++) {
                        pa[mt][0][h] += acc[mt][nt][0] * wtp[h][nt].x
                                      + acc[mt][nt][1] * wtp[h][nt].y;
                        pa[mt][1][h] += acc[mt][nt][2] * wtp[h][nt].x
                                      + acc[mt][nt][3] * wtp[h][nt].y;
                    }
                }
            #pragma unroll
            for (int mt = 0; mt < 2; mt++)
                #pragma unroll
                for (int p = 0; p < 2; p++)
                    #pragma unroll
                    for (int h = 0; h < 2; h++) {
                        float v = pa[mt][p][h];
                        v += __shfl_xor_sync(0xffffffffu, v, 1);
                        v += __shfl_xor_sync(0xffffffffu, v, 2);
                        pa[mt][p][h] = v;
                    }
            if (t == 0) {
                #pragma unroll
                for (int mt = 0; mt < 2; mt++)
                    #pragma unroll
                    for (int p = 0; p < 2; p++) {
                        int r = mt * 16 + g + 8 * p;
                        *(float2*)&sAp[r * 12 + wn * 2] =
                            make_float2(pa[mt][p][0], pa[mt][p][1]);
                    }
            }
        }
        if (lt == 0) sTile[grp] = atomicAdd(&g_tile, 1);
        GBAR();                               // bar3: sAp + sU[c^1] + ticket
        int nxt2 = sTile[grp];

        // ---- finish alpha, form m partials, reduce over g, atomics ----
        {
            float al[2][2][2];   // [mt][p][h]
            #pragma unroll
            for (int mt = 0; mt < 2; mt++)
                #pragma unroll
                for (int p = 0; p < 2; p++) {
                    int r = mt * 16 + g + 8 * p;
                    float2 f0 = *(const float2*)&sAp[r * 12 + 0];
                    float2 f1 = *(const float2*)&sAp[r * 12 + 2];
                    float2 f2 = *(const float2*)&sAp[r * 12 + 4];
                    float2 f3 = *(const float2*)&sAp[r * 12 + 6];
                    al[mt][p][0] = f0.x + f1.x + f2.x + f3.x + cc0;
                    al[mt][p][1] = f0.y + f1.y + f2.y + f3.y + cc1;
                }
            float pm[2][4][2];   // [h][nt][e]
            #pragma unroll
            for (int h = 0; h < 2; h++)
                #pragma unroll
                for (int nt = 0; nt < 4; nt++) {
                    pm[h][nt][0] = al[0][0][h] * acc[0][nt][0] + al[0][1][h] * acc[0][nt][2]
                                 + al[1][0][h] * acc[1][nt][0] + al[1][1][h] * acc[1][nt][2];
                    pm[h][nt][1] = al[0][0][h] * acc[0][nt][1] + al[0][1][h] * acc[0][nt][3]
                                 + al[1][0][h] * acc[1][nt][1] + al[1][1][h] * acc[1][nt][3];
                }
            #pragma unroll
            for (int h = 0; h < 2; h++)
                #pragma unroll
                for (int nt = 0; nt < 4; nt++)
                    #pragma unroll
                    for (int e = 0; e < 2; e++) {
                        float v = pm[h][nt][e];
                        v += __shfl_xor_sync(0xffffffffu, v, 4);
                        v += __shfl_xor_sync(0xffffffffu, v, 8);
                        v += __shfl_xor_sync(0xffffffffu, v, 16);
                        pm[h][nt][e] = v;
                    }
            if (g == 0) {
                #pragma unroll
                for (int h = 0; h < 2; h++)
                    #pragma unroll
                    for (int nt = 0; nt < 4; nt++)
                        #pragma unroll
                        for (int e = 0; e < 2; e++)
                            atomicAdd(&g_m[b * 256 + h * 128 + wn * 32 + nt * 8 + 2 * t + e],
                                      pm[h][nt][e]);
            }
            // abar: wn==0 warp covers all 32 rows exactly once
            if (wn == 0) {
                float s0 = al[0][0][0] + al[0][1][0] + al[1][0][0] + al[1][1][0];
                float s1 = al[0][0][1] + al[0][1][1] + al[1][0][1] + al[1][1][1];
                s0 += __shfl_xor_sync(0xffffffffu, s0, 4);
                s0 += __shfl_xor_sync(0xffffffffu, s0, 8);
                s0 += __shfl_xor_sync(0xffffffffu, s0, 16);
                s1 += __shfl_xor_sync(0xffffffffu, s1, 4);
                s1 += __shfl_xor_sync(0xffffffffu, s1, 8);
                s1 += __shfl_xor_sync(0xffffffffu, s1, 16);
                if (lane == 0) {
                    atomicAdd(&g_ab[b * 2 + 0], s0);
                    atomicAdd(&g_ab[b * 2 + 1], s1);
                }
            }
        }
        tile = nxt;
        nxt = nxt2;
        c ^= 1;
    }

    // ======== Exit protocol + distributed epilogue ========
    __syncthreads();   // join all groups
    if (tid == 0) { __threadfence(); sPrev = atomicAdd(&g_done, 1); }
    __syncthreads();
    int rank = sPrev;
    if (rank < EPI_RANK0) return;
    if (tid == 0) { while (atomicAdd(&g_done, 0) != GRID_MAIN) __nanosleep(64); }
    __syncthreads();
    __threadfence();

    int bb = rank - EPI_RANK0;   // 0..31, unique per epilogue block
    if (tid < 256) e_m[tid] = g_m[bb * 256 + tid];
    if (tid < 2) e_ab[tid] = g_ab[bb * 2 + tid];
    __syncthreads();
    if (tid < 256) g_m[bb * 256 + tid] = 0.f;   // restore for next replay
    if (tid < 2) g_ab[bb * 2 + tid] = 0.f;

    {   // ov[j] = (abar[h]*bv[j] + m[h][:] . Wv[:,j]) / N
        int j = tid & 127, qq = tid >> 7, h = j >> 6;
        float p = 0.f;
        #pragma unroll 4
        for (int pp = qq * 32; pp < qq * 32 + 32; pp++)
            p += e_m[h * 128 + pp] * __ldg(&Wv[pp * 128 + j]);
        e_p[tid] = p;
    }
    __syncthreads();
    if (tid < 128) {
        int h = tid >> 6;
        e_ov[tid] = (e_p[tid] + e_p[128 + tid] + e_p[256 + tid] + e_p[384 + tid]
                     + e_ab[h] * bv[tid]) * (1.0f / N_);
    }
    __syncthreads();
    {   // out[j] = bo[j] + ov . Wo[:,j]
        int j = tid & 127, qq = tid >> 7;
        float p = 0.f;
        #pragma unroll 4
        for (int pp = qq * 32; pp < qq * 32 + 32; pp++)
            p += e_ov[pp] * __ldg(&Wo[pp * 128 + j]);
        e_p[tid] = p;
    }
    __syncthreads();
    if (tid < 128)
        out[bb * 128 + tid] = e_p[tid] + e_p[128 + tid] + e_p[256 + tid]
                              + e_p[384 + tid] + bo[tid];

    if (tid == 0) {
        __threadfence();
        atomicAdd(&g_done2, 1);
        if (rank == GRID_MAIN - 1) {
            while (atomicAdd(&g_done2, 0) != EPI_BLOCKS) __nanosleep(64);
            g_tile = 0; g_done = 0; g_done2 = 0;
        }
    }
#undef GBAR
}

// ---------------------------------------------------------------------------
extern "C" void kernel_launch(void* const* d_in, const int* in_sizes, int n_in,
                              void* d_out, int out_size) {
    const float* u     = (const float*)d_in[0];
    // d_in[1] = x : unused by the reference
    const float* W1    = (const float*)d_in[2];
    const float* b1    = (const float*)d_in[3];
    const float* W2    = (const float*)d_in[4];
    const float* b2    = (const float*)d_in[5];
    const float* embed = (const float*)d_in[6];
    const float* Wq    = (const float*)d_in[7];
    const float* bq    = (const float*)d_in[8];
    const float* Wk    = (const float*)d_in[9];
    const float* bk    = (const float*)d_in[10];
    const float* Wv    = (const float*)d_in[11];
    const float* bv    = (const float*)d_in[12];
    const float* Wo    = (const float*)d_in[13];
    const float* bo    = (const float*)d_in[14];
    float* out = (float*)d_out;

    const size_t smem_bytes = (size_t)SMEM_FLOATS * sizeof(float);  // 128,032 B
    cudaFuncSetAttribute(main_kernel, cudaFuncAttributeMaxDynamicSharedMemorySize,
                         (int)smem_bytes);

    main_kernel<<<GRID_MAIN, 512, smem_bytes>>>(
        u, W1, b1, W2, b2, embed, Wq, bq, Wk, bk, Wv, bv, Wo, bo, out);
}